// round 7
// baseline (speedup 1.0000x reference)
#include <cuda_runtime.h>
#include <cuda_bf16.h>
#include <math.h>
#include <cstdint>

#define T_STEPS 240
#define BATCH   240
#define MPAD    256
#define INPUTD  256
#define HID     1024
#define NSTEPS  30
#define OUTD    8
#define WW      240
#define KTOT    1280
#define KCH     64
#define NCH_H   16          // serial chunks (K=1024, h only)
#define NCTA    128

// encoder smem: per chunk A 32KB (hi16+lo16) + B 16KB (hi8+lo8) = 48KB x3
#define BUFB   49152
#define SMEMB  (3 * BUFB)
// gx smem: B resident 64KB + A 3x32KB
#define GXSMEM (65536 + 3 * 32768)

// ---------------------------------------------------------------------------
// helpers
// ---------------------------------------------------------------------------
__device__ __forceinline__ uint32_t smem_to_u32(const void* p) {
    uint32_t a;
    asm("{ .reg .u64 t; cvta.to.shared.u64 t, %1; cvt.u32.u64 %0, t; }" : "=r"(a) : "l"(p));
    return a;
}

#define CP_ASYNC16(dst, src) \
    asm volatile("cp.async.cg.shared.global [%0], [%1], 16;" \
                 :: "r"(dst), "l"(__cvta_generic_to_global(src)))
#define CP_COMMIT() asm volatile("cp.async.commit_group;" ::: "memory")
#define CP_WAIT1()  asm volatile("cp.async.wait_group 1;" ::: "memory")
#define CP_WAIT0()  asm volatile("cp.async.wait_group 0;" ::: "memory")

#define LDSM4(r, addr) \
    asm volatile("ldmatrix.sync.aligned.m8n8.x4.shared.b16 {%0,%1,%2,%3}, [%4];" \
                 : "=r"((r)[0]), "=r"((r)[1]), "=r"((r)[2]), "=r"((r)[3]) : "r"(addr))

#define MMA16816(d, a, b) \
    asm volatile("mma.sync.aligned.m16n8k16.row.col.f32.bf16.bf16.f32 " \
                 "{%0,%1,%2,%3}, {%4,%5,%6,%7}, {%8,%9}, {%0,%1,%2,%3};" \
                 : "+f"((d)[0]), "+f"((d)[1]), "+f"((d)[2]), "+f"((d)[3]) \
                 : "r"((a)[0]), "r"((a)[1]), "r"((a)[2]), "r"((a)[3]), \
                   "r"((b)[0]), "r"((b)[1]))

// ---------------------------------------------------------------------------
// device scratch
// ---------------------------------------------------------------------------
__device__ __align__(256) __nv_bfloat16 g_W_hi[4096 * KTOT];
__device__ __align__(256) __nv_bfloat16 g_W_lo[4096 * KTOT];
__device__ __align__(256) __nv_bfloat16 g_x_hi[(size_t)T_STEPS * MPAD * INPUTD];
__device__ __align__(256) __nv_bfloat16 g_x_lo[(size_t)T_STEPS * MPAD * INPUTD];
__device__ __align__(256) __nv_bfloat16 g_hA_hi[2][MPAD * HID];
__device__ __align__(256) __nv_bfloat16 g_hA_lo[2][MPAD * HID];
__device__ __align__(256) float g_gx[(size_t)T_STEPS * MPAD * 4096];   // x @ Wih^T, fp32
__device__ __align__(256) float g_c[MPAD * HID];
__device__ __align__(16) float g_bias[4 * HID];

__device__ __align__(16) float g_u[OUTD];
__device__ __align__(16) float g_hdec[HID];
__device__ __align__(16) float g_comb[HID];
__device__ __align__(16) float g_gi[3 * HID];
__device__ __align__(16) float g_gh[3 * HID];
__device__ __align__(16) float g_v[HID + OUTD];    // [u; hdec]
__device__ __align__(16) float g_v2[HID + OUTD];   // [u; applied]
__device__ float g_sc[WW];
__device__ float g_aw[WW];

__device__ unsigned g_bcnt = 0;
__device__ volatile unsigned g_bgen = 0;

__device__ __forceinline__ void gbar(unsigned nctas) {
    __syncthreads();
    if (threadIdx.x == 0) {
        __threadfence();
        unsigned gen = g_bgen;
        if (atomicAdd(&g_bcnt, 1u) == nctas - 1u) {
            g_bcnt = 0;
            __threadfence();
            g_bgen = gen + 1u;
        } else {
            while (g_bgen == gen) __nanosleep(32);
        }
        __threadfence();
    }
    __syncthreads();
}

__device__ __forceinline__ float sigf(float x)  { return __fdividef(1.f, 1.f + __expf(-x)); }
__device__ __forceinline__ float tanhf_fast(float x) { return 1.f - __fdividef(2.f, __expf(2.f * x) + 1.f); }
__device__ __forceinline__ float warp_red(float s) {
#pragma unroll
    for (int o = 16; o; o >>= 1) s += __shfl_down_sync(0xffffffffu, s, o);
    return s;
}
__device__ __forceinline__ float ctx_at(size_t idx) {
    return __bfloat162float(g_hA_hi[0][idx]) + __bfloat162float(g_hA_lo[0][idx]);
}

// ---------------------------------------------------------------------------
// fragment machinery (32m x 32n warp tile, bf16x3)
// ---------------------------------------------------------------------------
struct Frag {
    uint32_t ah[2][4], al[2][4], bh[4][2], bl[4][2];
};

__device__ __forceinline__ void load_frags(Frag& f, uint32_t Ah, uint32_t Al,
                                           uint32_t Bh, uint32_t Bl,
                                           int ks, int wr, int wc, int lane) {
#pragma unroll
    for (int mt = 0; mt < 2; mt++) {
        int r = wr * 32 + mt * 16 + (lane & 15);
        uint32_t ch = ((uint32_t)((ks * 2 + (lane >> 4)) ^ (r & 7))) << 4;
        LDSM4(f.ah[mt], Ah + r * 128 + ch);
        LDSM4(f.al[mt], Al + r * 128 + ch);
    }
#pragma unroll
    for (int gp = 0; gp < 2; gp++) {
        int rn = (gp * 2 + (lane >> 4)) * 16 + wc * 8 + (lane & 7);
        uint32_t ch = ((uint32_t)((ks * 2 + ((lane >> 3) & 1)) ^ (rn & 7))) << 4;
        LDSM4(&f.bh[gp * 2][0], Bh + rn * 128 + ch);
        LDSM4(&f.bl[gp * 2][0], Bl + rn * 128 + ch);
    }
}

// pass-outer ordering: 8 independent accumulators between dependent reuses,
// so HMMA latency (~16-24cy) is fully hidden by the 8-MMA issue window.
__device__ __forceinline__ void do_mmas(float (&acc)[2][4][4], const Frag& f) {
#pragma unroll
    for (int mt = 0; mt < 2; mt++)
#pragma unroll
        for (int q = 0; q < 4; q++)
            MMA16816(acc[mt][q], f.ah[mt], f.bh[q]);
#pragma unroll
    for (int mt = 0; mt < 2; mt++)
#pragma unroll
        for (int q = 0; q < 4; q++)
            MMA16816(acc[mt][q], f.ah[mt], f.bl[q]);
#pragma unroll
    for (int mt = 0; mt < 2; mt++)
#pragma unroll
        for (int q = 0; q < 4; q++)
            MMA16816(acc[mt][q], f.al[mt], f.bh[q]);
}

// ---------------------------------------------------------------------------
// init / convert
// ---------------------------------------------------------------------------
__global__ void k_init(const float* __restrict__ bih, const float* __restrict__ bhh) {
    int i = blockIdx.x * blockDim.x + threadIdx.x;
    int n = MPAD * HID;
    __nv_bfloat16 z = __float2bfloat16(0.f);
    for (int j = i; j < n; j += gridDim.x * blockDim.x) {
        g_c[j] = 0.f;
        g_hA_hi[0][j] = z; g_hA_hi[1][j] = z;
        g_hA_lo[0][j] = z; g_hA_lo[1][j] = z;
    }
    if (i < 4 * HID) g_bias[i] = bih[i] + bhh[i];
}

__global__ void k_conv_w(const float* __restrict__ Whh, const float* __restrict__ Wih) {
    size_t i = (size_t)blockIdx.x * blockDim.x + threadIdx.x;
    if (i >= (size_t)4096 * KTOT) return;
    int r = (int)(i / KTOT);
    int k = (int)(i % KTOT);
    float v = (k < HID) ? Whh[(size_t)r * HID + k] : Wih[(size_t)r * INPUTD + (k - HID)];
    __nv_bfloat16 hi = __float2bfloat16(v);
    g_W_hi[i] = hi;
    g_W_lo[i] = __float2bfloat16(v - __bfloat162float(hi));
}

__global__ void k_conv_x(const float* __restrict__ data) {
    size_t i = (size_t)blockIdx.x * blockDim.x + threadIdx.x;
    if (i >= (size_t)T_STEPS * MPAD * INPUTD) return;
    int k = (int)(i % INPUTD);
    int b = (int)((i / INPUTD) % MPAD);
    int t = (int)(i / ((size_t)MPAD * INPUTD));
    float v = (b < BATCH) ? data[((size_t)t * BATCH + b) * INPUTD + k] : 0.f;
    __nv_bfloat16 hi = __float2bfloat16(v);
    g_x_hi[i] = hi;
    g_x_lo[i] = __float2bfloat16(v - __bfloat162float(hi));
}

// ---------------------------------------------------------------------------
// k_gx: Gx[t] = x_t @ Wih^T for all t.  128 persistent CTAs, weights resident.
// ---------------------------------------------------------------------------
__global__ __launch_bounds__(256, 1) void k_gx() {
    extern __shared__ __align__(128) char smem[];
    const uint32_t sb  = smem_to_u32(smem);
    const uint32_t sbB = sb;
    const uint32_t sbA = sb + 65536;
    const int tid  = threadIdx.x;
    const int lane = tid & 31;
    const int wid  = tid >> 5;
    const int wr   = wid & 3;
    const int wc   = wid >> 2;
    const int n0   = (blockIdx.x & 63) * 16;
    const int m0   = (blockIdx.x >> 6) * 128;
    const int rowq = lane >> 2;
    const int col2 = (lane & 3) * 2;

    // resident B: Wih K-slices (k = 1024 + ci*64), 4 chunks of 16KB (hi8+lo8)
#pragma unroll
    for (int i = tid; i < 2048; i += 256) {
        int ci = i >> 9, r = (i >> 3) & 63, ch = i & 7;
        int wrow = (r >> 4) * HID + n0 + (r & 15);
        size_t off = (size_t)wrow * KTOT + HID + ci * 64 + ch * 8;
        uint32_t dst = sbB + ci * 16384 + r * 128 + (((uint32_t)(ch ^ (r & 7))) << 4);
        CP_ASYNC16(dst, g_W_hi + off);
        CP_ASYNC16(dst + 8192, g_W_lo + off);
    }
    CP_COMMIT();

    auto loadA = [&](int lin) {
        int t = lin >> 2, ci = lin & 3;
        uint32_t base = sbA + (lin % 3) * 32768;
#pragma unroll
        for (int i = tid; i < 1024; i += 256) {
            int r = i >> 3, ch = i & 7;
            size_t off = ((size_t)t * MPAD + m0 + r) * INPUTD + ci * 64 + ch * 8;
            uint32_t dst = base + r * 128 + (((uint32_t)(ch ^ (r & 7))) << 4);
            CP_ASYNC16(dst, g_x_hi + off);
            CP_ASYNC16(dst + 16384, g_x_lo + off);
        }
        CP_COMMIT();
    };

    loadA(0); loadA(1);
    Frag fr[2];

    for (int t = 0; t < T_STEPS; t++) {
        float acc[2][4][4];
#pragma unroll
        for (int mt = 0; mt < 2; mt++)
#pragma unroll
            for (int q = 0; q < 4; q++)
#pragma unroll
                for (int j = 0; j < 4; j++) acc[mt][q][j] = 0.f;

        for (int ci = 0; ci < 4; ci++) {
            int lin = t * 4 + ci;
            if (lin == T_STEPS * 4 - 1) { CP_WAIT0(); } else { CP_WAIT1(); }
            __syncthreads();
            if (lin + 2 < T_STEPS * 4) loadA(lin + 2);

            const uint32_t Ab = sbA + (lin % 3) * 32768;
            const uint32_t Ah = Ab, Al = Ab + 16384;
            const uint32_t Bh = sbB + ci * 16384, Bl = Bh + 8192;

            load_frags(fr[0], Ah, Al, Bh, Bl, 0, wr, wc, lane);
#pragma unroll
            for (int ks = 0; ks < 4; ks++) {
                if (ks < 3) load_frags(fr[(ks + 1) & 1], Ah, Al, Bh, Bl, ks + 1, wr, wc, lane);
                do_mmas(acc, fr[ks & 1]);
            }
        }

        float* gx = g_gx + (size_t)t * MPAD * 4096;
#pragma unroll
        for (int mt = 0; mt < 2; mt++)
#pragma unroll
            for (int rp = 0; rp < 2; rp++) {
                int m = m0 + wr * 32 + mt * 16 + rowq + rp * 8;
#pragma unroll
                for (int q = 0; q < 4; q++) {
                    int col = q * 1024 + n0 + wc * 8 + col2;
                    *(float2*)&gx[(size_t)m * 4096 + col] =
                        make_float2(acc[mt][q][rp * 2], acc[mt][q][rp * 2 + 1]);
                }
            }
    }
}

// ---------------------------------------------------------------------------
// k_enc: persistent, 240 LSTM steps, K=1024 (h only), acc init from Gx.
// 128 CTAs x 256 thr (8 warps, 32x32 warp tiles).
// ---------------------------------------------------------------------------
__global__ __launch_bounds__(256, 1) void k_enc() {
    extern __shared__ __align__(128) char smem[];
    const uint32_t sb = smem_to_u32(smem);
    const int tid  = threadIdx.x;
    const int lane = tid & 31;
    const int wid  = tid >> 5;
    const int wr   = wid & 3;
    const int wc   = wid >> 2;
    const int n0   = (blockIdx.x & 63) * 16;
    const int m0   = (blockIdx.x >> 6) * 128;
    const int rowq = lane >> 2;
    const int col2 = (lane & 3) * 2;

    for (int t = 0; t < T_STEPS; t++) {
        const int par = t & 1;
        const __nv_bfloat16* __restrict__ hHi = g_hA_hi[par];
        const __nv_bfloat16* __restrict__ hLo = g_hA_lo[par];

        auto load_chunk = [&](int c) {
            const uint32_t base = sb + (c % 3) * BUFB;
            const int k0 = c * KCH;
#pragma unroll
            for (int i = tid; i < 1024; i += 256) {
                int r = i >> 3, ch = i & 7;
                uint32_t dst = base + r * 128 + (((uint32_t)(ch ^ (r & 7))) << 4);
                size_t off = (size_t)(m0 + r) * HID + k0 + ch * 8;
                CP_ASYNC16(dst,         hHi + off);
                CP_ASYNC16(dst + 16384, hLo + off);
            }
#pragma unroll
            for (int i = tid; i < 512; i += 256) {
                int r = i >> 3, ch = i & 7;
                uint32_t dst = base + 32768 + r * 128 + (((uint32_t)(ch ^ (r & 7))) << 4);
                int wrow = (r >> 4) * HID + n0 + (r & 15);
                size_t off = (size_t)wrow * KTOT + k0 + ch * 8;
                CP_ASYNC16(dst,        g_W_hi + off);
                CP_ASYNC16(dst + 8192, g_W_lo + off);
            }
            CP_COMMIT();
        };

        load_chunk(0);
        load_chunk(1);

        // init accumulators from precomputed x @ Wih^T
        float acc[2][4][4];
        {
            const float* gx = g_gx + (size_t)t * MPAD * 4096;
#pragma unroll
            for (int mt = 0; mt < 2; mt++)
#pragma unroll
                for (int rp = 0; rp < 2; rp++) {
                    int m = m0 + wr * 32 + mt * 16 + rowq + rp * 8;
#pragma unroll
                    for (int q = 0; q < 4; q++) {
                        int col = q * 1024 + n0 + wc * 8 + col2;
                        float2 v = *(const float2*)&gx[(size_t)m * 4096 + col];
                        acc[mt][q][rp * 2]     = v.x;
                        acc[mt][q][rp * 2 + 1] = v.y;
                    }
                }
        }

        Frag fr[2];
        for (int c = 0; c < NCH_H; c++) {
            if (c == NCH_H - 1) { CP_WAIT0(); } else { CP_WAIT1(); }
            __syncthreads();
            if (c + 2 < NCH_H) load_chunk(c + 2);

            const uint32_t base = sb + (c % 3) * BUFB;
            const uint32_t Ah = base, Al = base + 16384, Bh = base + 32768, Bl = base + 40960;

            load_frags(fr[0], Ah, Al, Bh, Bl, 0, wr, wc, lane);
#pragma unroll
            for (int ks = 0; ks < 4; ks++) {
                if (ks < 3) load_frags(fr[(ks + 1) & 1], Ah, Al, Bh, Bl, ks + 1, wr, wc, lane);
                do_mmas(acc, fr[ks & 1]);
            }
        }

        // fused LSTM gate epilogue
        __nv_bfloat16* __restrict__ oHi = g_hA_hi[par ^ 1];
        __nv_bfloat16* __restrict__ oLo = g_hA_lo[par ^ 1];
#pragma unroll
        for (int mt = 0; mt < 2; mt++)
#pragma unroll
            for (int rp = 0; rp < 2; rp++) {
                int m = m0 + wr * 32 + mt * 16 + rowq + rp * 8;
                if (m < BATCH) {
                    int n = n0 + wc * 8 + col2;
                    size_t idx = (size_t)m * HID + n;
                    float2 cold = *(float2*)&g_c[idx];
                    float2 bi = *(const float2*)&g_bias[n];
                    float2 bf = *(const float2*)&g_bias[HID + n];
                    float2 bg = *(const float2*)&g_bias[2 * HID + n];
                    float2 bo = *(const float2*)&g_bias[3 * HID + n];
                    float h[2], cn[2];
#pragma unroll
                    for (int j = 0; j < 2; j++) {
                        float gi = acc[mt][0][rp * 2 + j] + (j ? bi.y : bi.x);
                        float gf = acc[mt][1][rp * 2 + j] + (j ? bf.y : bf.x);
                        float gg = acc[mt][2][rp * 2 + j] + (j ? bg.y : bg.x);
                        float go = acc[mt][3][rp * 2 + j] + (j ? bo.y : bo.x);
                        cn[j] = sigf(gf) * (j ? cold.y : cold.x) + sigf(gi) * tanhf_fast(gg);
                        h[j]  = sigf(go) * tanhf_fast(cn[j]);
                    }
                    *(float2*)&g_c[idx] = make_float2(cn[0], cn[1]);
                    __nv_bfloat16 h0 = __float2bfloat16(h[0]);
                    __nv_bfloat16 h1 = __float2bfloat16(h[1]);
                    *(__nv_bfloat162*)&oHi[idx] = __halves2bfloat162(h0, h1);
                    *(__nv_bfloat162*)&oLo[idx] = __halves2bfloat162(
                        __float2bfloat16(h[0] - __bfloat162float(h0)),
                        __float2bfloat16(h[1] - __bfloat162float(h1)));
                }
            }

        gbar(NCTA);
    }
}

// ---------------------------------------------------------------------------
// k_dec: persistent decoder, 128 CTAs x 256 thr, float4 matvecs.
// ---------------------------------------------------------------------------
__global__ __launch_bounds__(256, 1) void k_dec(
    const float* __restrict__ attn_W, const float* __restrict__ attn_b,
    const float* __restrict__ comb_W, const float* __restrict__ comb_b,
    const float* __restrict__ gWih,   const float* __restrict__ gWhh,
    const float* __restrict__ gbih,   const float* __restrict__ gbhh,
    const float* __restrict__ out_W,  const float* __restrict__ out_b,
    float* __restrict__ outp)
{
    const int tid  = threadIdx.x;
    const int bid  = blockIdx.x;
    const int lane = tid & 31;
    const int warp = tid >> 5;
    const int gw   = bid * 8 + warp;   // 0..1023

    if (bid == 0) {
        for (int i = tid; i < HID; i += 256) {
            float v = ctx_at((size_t)(BATCH - 1) * HID + i);
            g_hdec[i] = v;
            g_v[OUTD + i] = v;
        }
        if (tid < OUTD) { g_u[tid] = 0.125f; g_v[tid] = 0.125f; g_v2[tid] = 0.125f; }
    }
    gbar(NCTA);

    for (int step = 0; step < NSTEPS; step++) {
        // ph1: attention scores
        if (gw < WW) {
            const float4* row = (const float4*)(attn_W + (size_t)gw * (HID + OUTD));
            const float4* v   = (const float4*)g_v;
            float s = 0.f;
            for (int k = lane; k < (HID + OUTD) / 4; k += 32) {
                float4 w = row[k], x = v[k];
                s += w.x * x.x + w.y * x.y + w.z * x.z + w.w * x.w;
            }
            s = warp_red(s);
            if (!lane) g_sc[gw] = s + attn_b[gw];
        }
        gbar(NCTA);

        // ph2: softmax (CTA 0)
        if (bid == 0) {
            __shared__ float rbuf[8];
            float x = (tid < WW) ? g_sc[tid] : -1e30f;
            float mx = x;
#pragma unroll
            for (int o = 16; o; o >>= 1) mx = fmaxf(mx, __shfl_xor_sync(0xffffffffu, mx, o));
            if (!lane) rbuf[warp] = mx;
            __syncthreads();
            float bm = rbuf[0];
#pragma unroll
            for (int i = 1; i < 8; i++) bm = fmaxf(bm, rbuf[i]);
            float e = (tid < WW) ? __expf(x - bm) : 0.f;
            float sm = e;
#pragma unroll
            for (int o = 16; o; o >>= 1) sm += __shfl_xor_sync(0xffffffffu, sm, o);
            __syncthreads();
            if (!lane) rbuf[warp] = sm;
            __syncthreads();
            float tot = 0.f;
#pragma unroll
            for (int i = 0; i < 8; i++) tot += rbuf[i];
            if (tid < WW) g_aw[tid] = e / tot;
        }
        gbar(NCTA);

        // ph3: applied = aw @ ctx -> g_v2[OUTD + n]
        {
            int n = gw;
            float s = 0.f;
            for (int j = lane; j < WW; j += 32) s += g_aw[j] * ctx_at((size_t)j * HID + n);
            s = warp_red(s);
            if (!lane) g_v2[OUTD + n] = s;
        }
        gbar(NCTA);

        // ph4: comb = relu(comb_W @ v2 + b)
        {
            const float4* row = (const float4*)(comb_W + (size_t)gw * (HID + OUTD));
            const float4* v   = (const float4*)g_v2;
            float s = 0.f;
            for (int k = lane; k < (HID + OUTD) / 4; k += 32) {
                float4 w = row[k], x = v[k];
                s += w.x * x.x + w.y * x.y + w.z * x.z + w.w * x.w;
            }
            s = warp_red(s);
            if (!lane) g_comb[gw] = fmaxf(s + comb_b[gw], 0.f);
        }
        gbar(NCTA);

        // ph5: gi / gh (6144 rows over 1024 warps)
        for (int rr = gw; rr < 6 * HID; rr += 1024) {
            const float4* row;
            const float4* v;
            if (rr < 3 * HID) {
                row = (const float4*)(gWih + (size_t)rr * HID);
                v = (const float4*)g_comb;
            } else {
                row = (const float4*)(gWhh + (size_t)(rr - 3 * HID) * HID);
                v = (const float4*)g_hdec;
            }
            float s = 0.f;
            for (int k = lane; k < HID / 4; k += 32) {
                float4 w = row[k], x = v[k];
                s += w.x * x.x + w.y * x.y + w.z * x.z + w.w * x.w;
            }
            s = warp_red(s);
            if (!lane) {
                if (rr < 3 * HID) g_gi[rr] = s + gbih[rr];
                else              g_gh[rr - 3 * HID] = s + gbhh[rr - 3 * HID];
            }
        }
        gbar(NCTA);

        // ph6: gate update + output head + next-step vector (CTA 0)
        if (bid == 0) {
            for (int n = tid; n < HID; n += 256) {
                float r  = sigf(g_gi[n] + g_gh[n]);
                float z  = sigf(g_gi[HID + n] + g_gh[HID + n]);
                float nn = tanhf_fast(g_gi[2 * HID + n] + r * g_gh[2 * HID + n]);
                g_hdec[n] = (1.f - z) * nn + z * g_hdec[n];
            }
            __syncthreads();
            __shared__ float lg[OUTD];
            if (warp < OUTD) {
                const float4* row = (const float4*)(out_W + (size_t)warp * HID);
                const float4* v   = (const float4*)g_hdec;
                float s = 0.f;
                for (int k = lane; k < HID / 4; k += 32) {
                    float4 w = row[k], x = v[k];
                    s += w.x * x.x + w.y * x.y + w.z * x.z + w.w * x.w;
                }
                s = warp_red(s);
                if (!lane) lg[warp] = s + out_b[warp];
            }
            __syncthreads();
            if (tid == 0) {
                float mx = -1e30f;
#pragma unroll
                for (int i = 0; i < OUTD; i++) mx = fmaxf(mx, lg[i]);
                float sum = 0.f;
#pragma unroll
                for (int i = 0; i < OUTD; i++) sum += __expf(lg[i] - mx);
                float lse = mx + __logf(sum);
#pragma unroll
                for (int i = 0; i < OUTD; i++) {
                    float lp = lg[i] - lse;
                    outp[step * OUTD + i] = lp;
                    g_u[i] = lp;
                }
            }
            __syncthreads();
            for (int i = tid; i < HID; i += 256) g_v[OUTD + i] = g_hdec[i];
            if (tid < OUTD) { float u = g_u[tid]; g_v[tid] = u; g_v2[tid] = u; }
        }
        gbar(NCTA);
    }
}

// ---------------------------------------------------------------------------
// launch
// ---------------------------------------------------------------------------
extern "C" void kernel_launch(void* const* d_in, const int* in_sizes, int n_in,
                              void* d_out, int out_size) {
    const float* data     = (const float*)d_in[0];
    const float* enc_Wih  = (const float*)d_in[1];
    const float* enc_Whh  = (const float*)d_in[2];
    const float* enc_bih  = (const float*)d_in[3];
    const float* enc_bhh  = (const float*)d_in[4];
    const float* attn_W   = (const float*)d_in[5];
    const float* attn_b   = (const float*)d_in[6];
    const float* comb_W   = (const float*)d_in[7];
    const float* comb_b   = (const float*)d_in[8];
    const float* gru_Wih  = (const float*)d_in[9];
    const float* gru_Whh  = (const float*)d_in[10];
    const float* gru_bih  = (const float*)d_in[11];
    const float* gru_bhh  = (const float*)d_in[12];
    const float* out_W    = (const float*)d_in[13];
    const float* out_b    = (const float*)d_in[14];
    float* out = (float*)d_out;

    cudaFuncSetAttribute(k_enc, cudaFuncAttributeMaxDynamicSharedMemorySize, SMEMB);
    cudaFuncSetAttribute(k_gx,  cudaFuncAttributeMaxDynamicSharedMemorySize, GXSMEM);

    k_init<<<1024, 256>>>(enc_bih, enc_bhh);
    k_conv_w<<<(4096 * KTOT + 255) / 256, 256>>>(enc_Whh, enc_Wih);
    k_conv_x<<<(T_STEPS * MPAD * INPUTD + 255) / 256, 256>>>(data);

    k_gx<<<NCTA, 256, GXSMEM>>>();
    k_enc<<<NCTA, 256, SMEMB>>>();

    k_dec<<<NCTA, 256>>>(attn_W, attn_b, comb_W, comb_b,
                         gru_Wih, gru_Whh, gru_bih, gru_bhh,
                         out_W, out_b, out);
}

// round 8
// speedup vs baseline: 1.2711x; 1.2711x over previous
#include <cuda_runtime.h>
#include <cuda_fp16.h>
#include <math.h>
#include <cstdint>

#define T_STEPS 240
#define BATCH   240
#define MPAD    256
#define INPUTD  256
#define HID     1024
#define NSTEPS  30
#define OUTD    8
#define WW      240
#define KTOT    1280
#define KCH     64
#define NCH_H   16          // serial chunks (K=1024, h only)
#define NCTA    128

// encoder smem per chunk: A 16KB (fp16) | B_hi 8KB | B_lo 8KB = 32KB, x3
#define BUFB   32768
#define SMEMB  (3 * BUFB)
// gx smem: B resident 64KB + A 3x16KB
#define GXSMEM (65536 + 3 * 16384)

// ---------------------------------------------------------------------------
// helpers
// ---------------------------------------------------------------------------
__device__ __forceinline__ uint32_t smem_to_u32(const void* p) {
    uint32_t a;
    asm("{ .reg .u64 t; cvta.to.shared.u64 t, %1; cvt.u32.u64 %0, t; }" : "=r"(a) : "l"(p));
    return a;
}

#define CP_ASYNC16(dst, src) \
    asm volatile("cp.async.cg.shared.global [%0], [%1], 16;" \
                 :: "r"(dst), "l"(__cvta_generic_to_global(src)))
#define CP_COMMIT() asm volatile("cp.async.commit_group;" ::: "memory")
#define CP_WAIT1()  asm volatile("cp.async.wait_group 1;" ::: "memory")
#define CP_WAIT0()  asm volatile("cp.async.wait_group 0;" ::: "memory")

#define LDSM4(r, addr) \
    asm volatile("ldmatrix.sync.aligned.m8n8.x4.shared.b16 {%0,%1,%2,%3}, [%4];" \
                 : "=r"((r)[0]), "=r"((r)[1]), "=r"((r)[2]), "=r"((r)[3]) : "r"(addr))

#define MMA16816(d, a, b) \
    asm volatile("mma.sync.aligned.m16n8k16.row.col.f32.f16.f16.f32 " \
                 "{%0,%1,%2,%3}, {%4,%5,%6,%7}, {%8,%9}, {%0,%1,%2,%3};" \
                 : "+f"((d)[0]), "+f"((d)[1]), "+f"((d)[2]), "+f"((d)[3]) \
                 : "r"((a)[0]), "r"((a)[1]), "r"((a)[2]), "r"((a)[3]), \
                   "r"((b)[0]), "r"((b)[1]))

// ---------------------------------------------------------------------------
// device scratch
// ---------------------------------------------------------------------------
__device__ __align__(256) __half g_W_hi[4096 * KTOT];
__device__ __align__(256) __half g_W_lo[4096 * KTOT];
__device__ __align__(256) __half g_x[(size_t)T_STEPS * MPAD * INPUTD];
__device__ __align__(256) __half g_h[2][MPAD * HID];
__device__ __align__(256) float g_gx[(size_t)T_STEPS * MPAD * 4096];   // x @ Wih^T, fp32
__device__ __align__(256) float g_c[MPAD * HID];
__device__ __align__(16) float g_bias[4 * HID];

__device__ __align__(16) float g_u[OUTD];
__device__ __align__(16) float g_hdec[HID];
__device__ __align__(16) float g_comb[HID];
__device__ __align__(16) float g_gi[3 * HID];
__device__ __align__(16) float g_gh[3 * HID];
__device__ __align__(16) float g_v[HID + OUTD];    // [u; hdec]
__device__ __align__(16) float g_v2[HID + OUTD];   // [u; applied]
__device__ float g_sc[WW];
__device__ float g_aw[WW];

__device__ unsigned g_bcnt = 0;
__device__ volatile unsigned g_bgen = 0;

__device__ __forceinline__ void gbar(unsigned nctas) {
    __syncthreads();
    if (threadIdx.x == 0) {
        __threadfence();
        unsigned gen = g_bgen;
        if (atomicAdd(&g_bcnt, 1u) == nctas - 1u) {
            g_bcnt = 0;
            __threadfence();
            g_bgen = gen + 1u;
        } else {
            while (g_bgen == gen) __nanosleep(32);
        }
        __threadfence();
    }
    __syncthreads();
}

__device__ __forceinline__ float sigf(float x)  { return __fdividef(1.f, 1.f + __expf(-x)); }
__device__ __forceinline__ float tanhf_fast(float x) { return 1.f - __fdividef(2.f, __expf(2.f * x) + 1.f); }
__device__ __forceinline__ float warp_red(float s) {
#pragma unroll
    for (int o = 16; o; o >>= 1) s += __shfl_down_sync(0xffffffffu, s, o);
    return s;
}
__device__ __forceinline__ float ctx_at(size_t idx) {
    return __half2float(g_h[0][idx]);
}

// ---------------------------------------------------------------------------
// fragment machinery (32m x 32n warp tile, fp16x2: A single, B hi+lo)
// ---------------------------------------------------------------------------
struct Frag {
    uint32_t ah[2][4], bh[4][2], bl[4][2];
};

__device__ __forceinline__ void load_frags(Frag& f, uint32_t Ah,
                                           uint32_t Bh, uint32_t Bl,
                                           int ks, int wr, int wc, int lane) {
#pragma unroll
    for (int mt = 0; mt < 2; mt++) {
        int r = wr * 32 + mt * 16 + (lane & 15);
        uint32_t ch = ((uint32_t)((ks * 2 + (lane >> 4)) ^ (r & 7))) << 4;
        LDSM4(f.ah[mt], Ah + r * 128 + ch);
    }
#pragma unroll
    for (int gp = 0; gp < 2; gp++) {
        int rn = (gp * 2 + (lane >> 4)) * 16 + wc * 8 + (lane & 7);
        uint32_t ch = ((uint32_t)((ks * 2 + ((lane >> 3) & 1)) ^ (rn & 7))) << 4;
        LDSM4(&f.bh[gp * 2][0], Bh + rn * 128 + ch);
        LDSM4(&f.bl[gp * 2][0], Bl + rn * 128 + ch);
    }
}

__device__ __forceinline__ void do_mmas(float (&acc)[2][4][4], const Frag& f) {
#pragma unroll
    for (int mt = 0; mt < 2; mt++)
#pragma unroll
        for (int q = 0; q < 4; q++)
            MMA16816(acc[mt][q], f.ah[mt], f.bh[q]);
#pragma unroll
    for (int mt = 0; mt < 2; mt++)
#pragma unroll
        for (int q = 0; q < 4; q++)
            MMA16816(acc[mt][q], f.ah[mt], f.bl[q]);
}

// ---------------------------------------------------------------------------
// init / convert
// ---------------------------------------------------------------------------
__global__ void k_init(const float* __restrict__ bih, const float* __restrict__ bhh) {
    int i = blockIdx.x * blockDim.x + threadIdx.x;
    int n = MPAD * HID;
    __half z = __float2half(0.f);
    for (int j = i; j < n; j += gridDim.x * blockDim.x) {
        g_c[j] = 0.f;
        g_h[0][j] = z; g_h[1][j] = z;
    }
    if (i < 4 * HID) g_bias[i] = bih[i] + bhh[i];
}

__global__ void k_conv_w(const float* __restrict__ Whh, const float* __restrict__ Wih) {
    size_t i = (size_t)blockIdx.x * blockDim.x + threadIdx.x;
    if (i >= (size_t)4096 * KTOT) return;
    int r = (int)(i / KTOT);
    int k = (int)(i % KTOT);
    float v = (k < HID) ? Whh[(size_t)r * HID + k] : Wih[(size_t)r * INPUTD + (k - HID)];
    __half hi = __float2half(v);
    g_W_hi[i] = hi;
    g_W_lo[i] = __float2half(v - __half2float(hi));
}

__global__ void k_conv_x(const float* __restrict__ data) {
    size_t i = (size_t)blockIdx.x * blockDim.x + threadIdx.x;
    if (i >= (size_t)T_STEPS * MPAD * INPUTD) return;
    int k = (int)(i % INPUTD);
    int b = (int)((i / INPUTD) % MPAD);
    int t = (int)(i / ((size_t)MPAD * INPUTD));
    float v = (b < BATCH) ? data[((size_t)t * BATCH + b) * INPUTD + k] : 0.f;
    g_x[i] = __float2half(v);
}

// ---------------------------------------------------------------------------
// k_gx: Gx[t] = x_t @ Wih^T for all t.  128 persistent CTAs, weights resident.
// ---------------------------------------------------------------------------
__global__ __launch_bounds__(256, 1) void k_gx() {
    extern __shared__ __align__(128) char smem[];
    const uint32_t sb  = smem_to_u32(smem);
    const uint32_t sbB = sb;
    const uint32_t sbA = sb + 65536;
    const int tid  = threadIdx.x;
    const int lane = tid & 31;
    const int wid  = tid >> 5;
    const int wr   = wid & 3;
    const int wc   = wid >> 2;
    const int n0   = (blockIdx.x & 63) * 16;
    const int m0   = (blockIdx.x >> 6) * 128;
    const int rowq = lane >> 2;
    const int col2 = (lane & 3) * 2;

    // resident B: Wih K-slices (k = 1024 + ci*64), 4 chunks of 16KB (hi8+lo8)
#pragma unroll
    for (int i = tid; i < 2048; i += 256) {
        int ci = i >> 9, r = (i >> 3) & 63, ch = i & 7;
        int wrow = (r >> 4) * HID + n0 + (r & 15);
        size_t off = (size_t)wrow * KTOT + HID + ci * 64 + ch * 8;
        uint32_t dst = sbB + ci * 16384 + r * 128 + (((uint32_t)(ch ^ (r & 7))) << 4);
        CP_ASYNC16(dst, g_W_hi + off);
        CP_ASYNC16(dst + 8192, g_W_lo + off);
    }
    CP_COMMIT();

    auto loadA = [&](int lin) {
        int t = lin >> 2, ci = lin & 3;
        uint32_t base = sbA + (lin % 3) * 16384;
#pragma unroll
        for (int i = tid; i < 1024; i += 256) {
            int r = i >> 3, ch = i & 7;
            size_t off = ((size_t)t * MPAD + m0 + r) * INPUTD + ci * 64 + ch * 8;
            uint32_t dst = base + r * 128 + (((uint32_t)(ch ^ (r & 7))) << 4);
            CP_ASYNC16(dst, g_x + off);
        }
        CP_COMMIT();
    };

    loadA(0); loadA(1);
    Frag fr[2];

    for (int t = 0; t < T_STEPS; t++) {
        float acc[2][4][4];
#pragma unroll
        for (int mt = 0; mt < 2; mt++)
#pragma unroll
            for (int q = 0; q < 4; q++)
#pragma unroll
                for (int j = 0; j < 4; j++) acc[mt][q][j] = 0.f;

        for (int ci = 0; ci < 4; ci++) {
            int lin = t * 4 + ci;
            if (lin == T_STEPS * 4 - 1) { CP_WAIT0(); } else { CP_WAIT1(); }
            __syncthreads();
            if (lin + 2 < T_STEPS * 4) loadA(lin + 2);

            const uint32_t Ah = sbA + (lin % 3) * 16384;
            const uint32_t Bh = sbB + ci * 16384, Bl = Bh + 8192;

            load_frags(fr[0], Ah, Bh, Bl, 0, wr, wc, lane);
#pragma unroll
            for (int ks = 0; ks < 4; ks++) {
                if (ks < 3) load_frags(fr[(ks + 1) & 1], Ah, Bh, Bl, ks + 1, wr, wc, lane);
                do_mmas(acc, fr[ks & 1]);
            }
        }

        float* gx = g_gx + (size_t)t * MPAD * 4096;
#pragma unroll
        for (int mt = 0; mt < 2; mt++)
#pragma unroll
            for (int rp = 0; rp < 2; rp++) {
                int m = m0 + wr * 32 + mt * 16 + rowq + rp * 8;
#pragma unroll
                for (int q = 0; q < 4; q++) {
                    int col = q * 1024 + n0 + wc * 8 + col2;
                    *(float2*)&gx[(size_t)m * 4096 + col] =
                        make_float2(acc[mt][q][rp * 2], acc[mt][q][rp * 2 + 1]);
                }
            }
    }
}

// ---------------------------------------------------------------------------
// k_enc: persistent, 240 LSTM steps, K=1024 (h only), acc init from Gx.
// 128 CTAs x 256 thr (8 warps, 32x32 warp tiles), fp16x2 math.
// ---------------------------------------------------------------------------
__global__ __launch_bounds__(256, 1) void k_enc() {
    extern __shared__ __align__(128) char smem[];
    const uint32_t sb = smem_to_u32(smem);
    const int tid  = threadIdx.x;
    const int lane = tid & 31;
    const int wid  = tid >> 5;
    const int wr   = wid & 3;
    const int wc   = wid >> 2;
    const int n0   = (blockIdx.x & 63) * 16;
    const int m0   = (blockIdx.x >> 6) * 128;
    const int rowq = lane >> 2;
    const int col2 = (lane & 3) * 2;

    for (int t = 0; t < T_STEPS; t++) {
        const int par = t & 1;
        const __half* __restrict__ hIn = g_h[par];

        auto load_chunk = [&](int c) {
            const uint32_t base = sb + (c % 3) * BUFB;
            const int k0 = c * KCH;
#pragma unroll
            for (int i = tid; i < 1024; i += 256) {
                int r = i >> 3, ch = i & 7;
                uint32_t dst = base + r * 128 + (((uint32_t)(ch ^ (r & 7))) << 4);
                size_t off = (size_t)(m0 + r) * HID + k0 + ch * 8;
                CP_ASYNC16(dst, hIn + off);
            }
#pragma unroll
            for (int i = tid; i < 512; i += 256) {
                int r = i >> 3, ch = i & 7;
                uint32_t dst = base + 16384 + r * 128 + (((uint32_t)(ch ^ (r & 7))) << 4);
                int wrow = (r >> 4) * HID + n0 + (r & 15);
                size_t off = (size_t)wrow * KTOT + k0 + ch * 8;
                CP_ASYNC16(dst,        g_W_hi + off);
                CP_ASYNC16(dst + 8192, g_W_lo + off);
            }
            CP_COMMIT();
        };

        load_chunk(0);
        load_chunk(1);

        // init accumulators from precomputed x @ Wih^T
        float acc[2][4][4];
        {
            const float* gx = g_gx + (size_t)t * MPAD * 4096;
#pragma unroll
            for (int mt = 0; mt < 2; mt++)
#pragma unroll
                for (int rp = 0; rp < 2; rp++) {
                    int m = m0 + wr * 32 + mt * 16 + rowq + rp * 8;
#pragma unroll
                    for (int q = 0; q < 4; q++) {
                        int col = q * 1024 + n0 + wc * 8 + col2;
                        float2 v = *(const float2*)&gx[(size_t)m * 4096 + col];
                        acc[mt][q][rp * 2]     = v.x;
                        acc[mt][q][rp * 2 + 1] = v.y;
                    }
                }
        }

        Frag fr[2];
        for (int c = 0; c < NCH_H; c++) {
            if (c == NCH_H - 1) { CP_WAIT0(); } else { CP_WAIT1(); }
            __syncthreads();
            if (c + 2 < NCH_H) load_chunk(c + 2);

            const uint32_t base = sb + (c % 3) * BUFB;
            const uint32_t Ah = base, Bh = base + 16384, Bl = base + 24576;

            load_frags(fr[0], Ah, Bh, Bl, 0, wr, wc, lane);
#pragma unroll
            for (int ks = 0; ks < 4; ks++) {
                if (ks < 3) load_frags(fr[(ks + 1) & 1], Ah, Bh, Bl, ks + 1, wr, wc, lane);
                do_mmas(acc, fr[ks & 1]);
            }
        }

        // fused LSTM gate epilogue
        __half* __restrict__ hOut = g_h[par ^ 1];
#pragma unroll
        for (int mt = 0; mt < 2; mt++)
#pragma unroll
            for (int rp = 0; rp < 2; rp++) {
                int m = m0 + wr * 32 + mt * 16 + rowq + rp * 8;
                if (m < BATCH) {
                    int n = n0 + wc * 8 + col2;
                    size_t idx = (size_t)m * HID + n;
                    float2 cold = *(float2*)&g_c[idx];
                    float2 bi = *(const float2*)&g_bias[n];
                    float2 bf = *(const float2*)&g_bias[HID + n];
                    float2 bg = *(const float2*)&g_bias[2 * HID + n];
                    float2 bo = *(const float2*)&g_bias[3 * HID + n];
                    float h[2], cn[2];
#pragma unroll
                    for (int j = 0; j < 2; j++) {
                        float gi = acc[mt][0][rp * 2 + j] + (j ? bi.y : bi.x);
                        float gf = acc[mt][1][rp * 2 + j] + (j ? bf.y : bf.x);
                        float gg = acc[mt][2][rp * 2 + j] + (j ? bg.y : bg.x);
                        float go = acc[mt][3][rp * 2 + j] + (j ? bo.y : bo.x);
                        cn[j] = sigf(gf) * (j ? cold.y : cold.x) + sigf(gi) * tanhf_fast(gg);
                        h[j]  = sigf(go) * tanhf_fast(cn[j]);
                    }
                    *(float2*)&g_c[idx] = make_float2(cn[0], cn[1]);
                    *(__half2*)&hOut[idx] =
                        __halves2half2(__float2half(h[0]), __float2half(h[1]));
                }
            }

        gbar(NCTA);
    }
}

// ---------------------------------------------------------------------------
// k_dec: persistent decoder, 128 CTAs x 256 thr, float4 matvecs.
// ---------------------------------------------------------------------------
__global__ __launch_bounds__(256, 1) void k_dec(
    const float* __restrict__ attn_W, const float* __restrict__ attn_b,
    const float* __restrict__ comb_W, const float* __restrict__ comb_b,
    const float* __restrict__ gWih,   const float* __restrict__ gWhh,
    const float* __restrict__ gbih,   const float* __restrict__ gbhh,
    const float* __restrict__ out_W,  const float* __restrict__ out_b,
    float* __restrict__ outp)
{
    const int tid  = threadIdx.x;
    const int bid  = blockIdx.x;
    const int lane = tid & 31;
    const int warp = tid >> 5;
    const int gw   = bid * 8 + warp;   // 0..1023

    if (bid == 0) {
        for (int i = tid; i < HID; i += 256) {
            float v = ctx_at((size_t)(BATCH - 1) * HID + i);
            g_hdec[i] = v;
            g_v[OUTD + i] = v;
        }
        if (tid < OUTD) { g_u[tid] = 0.125f; g_v[tid] = 0.125f; g_v2[tid] = 0.125f; }
    }
    gbar(NCTA);

    for (int step = 0; step < NSTEPS; step++) {
        // ph1: attention scores
        if (gw < WW) {
            const float4* row = (const float4*)(attn_W + (size_t)gw * (HID + OUTD));
            const float4* v   = (const float4*)g_v;
            float s = 0.f;
            for (int k = lane; k < (HID + OUTD) / 4; k += 32) {
                float4 w = row[k], x = v[k];
                s += w.x * x.x + w.y * x.y + w.z * x.z + w.w * x.w;
            }
            s = warp_red(s);
            if (!lane) g_sc[gw] = s + attn_b[gw];
        }
        gbar(NCTA);

        // ph2: softmax (CTA 0)
        if (bid == 0) {
            __shared__ float rbuf[8];
            float x = (tid < WW) ? g_sc[tid] : -1e30f;
            float mx = x;
#pragma unroll
            for (int o = 16; o; o >>= 1) mx = fmaxf(mx, __shfl_xor_sync(0xffffffffu, mx, o));
            if (!lane) rbuf[warp] = mx;
            __syncthreads();
            float bm = rbuf[0];
#pragma unroll
            for (int i = 1; i < 8; i++) bm = fmaxf(bm, rbuf[i]);
            float e = (tid < WW) ? __expf(x - bm) : 0.f;
            float sm = e;
#pragma unroll
            for (int o = 16; o; o >>= 1) sm += __shfl_xor_sync(0xffffffffu, sm, o);
            __syncthreads();
            if (!lane) rbuf[warp] = sm;
            __syncthreads();
            float tot = 0.f;
#pragma unroll
            for (int i = 0; i < 8; i++) tot += rbuf[i];
            if (tid < WW) g_aw[tid] = e / tot;
        }
        gbar(NCTA);

        // ph3: applied = aw @ ctx -> g_v2[OUTD + n]
        {
            int n = gw;
            float s = 0.f;
            for (int j = lane; j < WW; j += 32) s += g_aw[j] * ctx_at((size_t)j * HID + n);
            s = warp_red(s);
            if (!lane) g_v2[OUTD + n] = s;
        }
        gbar(NCTA);

        // ph4: comb = relu(comb_W @ v2 + b)
        {
            const float4* row = (const float4*)(comb_W + (size_t)gw * (HID + OUTD));
            const float4* v   = (const float4*)g_v2;
            float s = 0.f;
            for (int k = lane; k < (HID + OUTD) / 4; k += 32) {
                float4 w = row[k], x = v[k];
                s += w.x * x.x + w.y * x.y + w.z * x.z + w.w * x.w;
            }
            s = warp_red(s);
            if (!lane) g_comb[gw] = fmaxf(s + comb_b[gw], 0.f);
        }
        gbar(NCTA);

        // ph5: gi / gh (6144 rows over 1024 warps)
        for (int rr = gw; rr < 6 * HID; rr += 1024) {
            const float4* row;
            const float4* v;
            if (rr < 3 * HID) {
                row = (const float4*)(gWih + (size_t)rr * HID);
                v = (const float4*)g_comb;
            } else {
                row = (const float4*)(gWhh + (size_t)(rr - 3 * HID) * HID);
                v = (const float4*)g_hdec;
            }
            float s = 0.f;
            for (int k = lane; k < HID / 4; k += 32) {
                float4 w = row[k], x = v[k];
                s += w.x * x.x + w.y * x.y + w.z * x.z + w.w * x.w;
            }
            s = warp_red(s);
            if (!lane) {
                if (rr < 3 * HID) g_gi[rr] = s + gbih[rr];
                else              g_gh[rr - 3 * HID] = s + gbhh[rr - 3 * HID];
            }
        }
        gbar(NCTA);

        // ph6: gate update + output head + next-step vector (CTA 0)
        if (bid == 0) {
            for (int n = tid; n < HID; n += 256) {
                float r  = sigf(g_gi[n] + g_gh[n]);
                float z  = sigf(g_gi[HID + n] + g_gh[HID + n]);
                float nn = tanhf_fast(g_gi[2 * HID + n] + r * g_gh[2 * HID + n]);
                g_hdec[n] = (1.f - z) * nn + z * g_hdec[n];
            }
            __syncthreads();
            __shared__ float lg[OUTD];
            if (warp < OUTD) {
                const float4* row = (const float4*)(out_W + (size_t)warp * HID);
                const float4* v   = (const float4*)g_hdec;
                float s = 0.f;
                for (int k = lane; k < HID / 4; k += 32) {
                    float4 w = row[k], x = v[k];
                    s += w.x * x.x + w.y * x.y + w.z * x.z + w.w * x.w;
                }
                s = warp_red(s);
                if (!lane) lg[warp] = s + out_b[warp];
            }
            __syncthreads();
            if (tid == 0) {
                float mx = -1e30f;
#pragma unroll
                for (int i = 0; i < OUTD; i++) mx = fmaxf(mx, lg[i]);
                float sum = 0.f;
#pragma unroll
                for (int i = 0; i < OUTD; i++) sum += __expf(lg[i] - mx);
                float lse = mx + __logf(sum);
#pragma unroll
                for (int i = 0; i < OUTD; i++) {
                    float lp = lg[i] - lse;
                    outp[step * OUTD + i] = lp;
                    g_u[i] = lp;
                }
            }
            __syncthreads();
            for (int i = tid; i < HID; i += 256) g_v[OUTD + i] = g_hdec[i];
            if (tid < OUTD) { float u = g_u[tid]; g_v[tid] = u; g_v2[tid] = u; }
        }
        gbar(NCTA);
    }
}

// ---------------------------------------------------------------------------
// launch
// ---------------------------------------------------------------------------
extern "C" void kernel_launch(void* const* d_in, const int* in_sizes, int n_in,
                              void* d_out, int out_size) {
    const float* data     = (const float*)d_in[0];
    const float* enc_Wih  = (const float*)d_in[1];
    const float* enc_Whh  = (const float*)d_in[2];
    const float* enc_bih  = (const float*)d_in[3];
    const float* enc_bhh  = (const float*)d_in[4];
    const float* attn_W   = (const float*)d_in[5];
    const float* attn_b   = (const float*)d_in[6];
    const float* comb_W   = (const float*)d_in[7];
    const float* comb_b   = (const float*)d_in[8];
    const float* gru_Wih  = (const float*)d_in[9];
    const float* gru_Whh  = (const float*)d_in[10];
    const float* gru_bih  = (const float*)d_in[11];
    const float* gru_bhh  = (const float*)d_in[12];
    const float* out_W    = (const float*)d_in[13];
    const float* out_b    = (const float*)d_in[14];
    float* out = (float*)d_out;

    cudaFuncSetAttribute(k_enc, cudaFuncAttributeMaxDynamicSharedMemorySize, SMEMB);
    cudaFuncSetAttribute(k_gx,  cudaFuncAttributeMaxDynamicSharedMemorySize, GXSMEM);

    k_init<<<1024, 256>>>(enc_bih, enc_bhh);
    k_conv_w<<<(4096 * KTOT + 255) / 256, 256>>>(enc_Whh, enc_Wih);
    k_conv_x<<<(T_STEPS * MPAD * INPUTD + 255) / 256, 256>>>(data);

    k_gx<<<NCTA, 256, GXSMEM>>>();
    k_enc<<<NCTA, 256, SMEMB>>>();

    k_dec<<<NCTA, 256>>>(attn_W, attn_b, comb_W, comb_b,
                         gru_Wih, gru_Whh, gru_bih, gru_bhh,
                         out_W, out_b, out);
}

// round 9
// speedup vs baseline: 1.6436x; 1.2930x over previous
#include <cuda_runtime.h>
#include <cuda_fp16.h>
#include <math.h>
#include <cstdint>

#define T_STEPS 240
#define BATCH   240
#define MPAD    256
#define INPUTD  256
#define HID     1024
#define NSTEPS  30
#define OUTD    8
#define WW      240
#define KTOT    1280
#define KCH     64
#define NCH_H   16          // serial chunks (K=1024, h only)
#define NCTA    128

// encoder smem per chunk: A 16KB (fp16) | B 8KB (fp16) = 24KB, x3
#define BUFB   24576
#define SMEMB  (3 * BUFB)
// gx smem: B resident 32KB + A 3x16KB
#define GXSMEM (32768 + 3 * 16384)

// ---------------------------------------------------------------------------
// helpers
// ---------------------------------------------------------------------------
__device__ __forceinline__ uint32_t smem_to_u32(const void* p) {
    uint32_t a;
    asm("{ .reg .u64 t; cvta.to.shared.u64 t, %1; cvt.u32.u64 %0, t; }" : "=r"(a) : "l"(p));
    return a;
}

#define CP_ASYNC16(dst, src) \
    asm volatile("cp.async.cg.shared.global [%0], [%1], 16;" \
                 :: "r"(dst), "l"(__cvta_generic_to_global(src)))
#define CP_COMMIT() asm volatile("cp.async.commit_group;" ::: "memory")
#define CP_WAIT1()  asm volatile("cp.async.wait_group 1;" ::: "memory")
#define CP_WAIT0()  asm volatile("cp.async.wait_group 0;" ::: "memory")

#define LDSM4(r, addr) \
    asm volatile("ldmatrix.sync.aligned.m8n8.x4.shared.b16 {%0,%1,%2,%3}, [%4];" \
                 : "=r"((r)[0]), "=r"((r)[1]), "=r"((r)[2]), "=r"((r)[3]) : "r"(addr))

#define MMA16816(d, a, b) \
    asm volatile("mma.sync.aligned.m16n8k16.row.col.f32.f16.f16.f32 " \
                 "{%0,%1,%2,%3}, {%4,%5,%6,%7}, {%8,%9}, {%0,%1,%2,%3};" \
                 : "+f"((d)[0]), "+f"((d)[1]), "+f"((d)[2]), "+f"((d)[3]) \
                 : "r"((a)[0]), "r"((a)[1]), "r"((a)[2]), "r"((a)[3]), \
                   "r"((b)[0]), "r"((b)[1]))

// ---------------------------------------------------------------------------
// device scratch
// ---------------------------------------------------------------------------
__device__ __align__(256) __half g_W[4096 * KTOT];
__device__ __align__(256) __half g_x[(size_t)T_STEPS * MPAD * INPUTD];
__device__ __align__(256) __half g_h[2][MPAD * HID];
__device__ __align__(256) float g_gx[(size_t)T_STEPS * MPAD * 4096];   // x @ Wih^T, fp32
__device__ __align__(256) float g_c[MPAD * HID];
__device__ __align__(16) float g_bias[4 * HID];

__device__ __align__(16) float g_u[OUTD];
__device__ __align__(16) float g_hdec[HID];
__device__ __align__(16) float g_comb[HID];
__device__ __align__(16) float g_gi[3 * HID];
__device__ __align__(16) float g_gh[3 * HID];
__device__ __align__(16) float g_v[HID + OUTD];    // [u; hdec]
__device__ __align__(16) float g_v2[HID + OUTD];   // [u; applied]
__device__ float g_sc[WW];
__device__ float g_aw[WW];

__device__ unsigned g_bcnt = 0;
__device__ volatile unsigned g_bgen = 0;

__device__ __forceinline__ void gbar(unsigned nctas) {
    __syncthreads();
    if (threadIdx.x == 0) {
        __threadfence();
        unsigned gen = g_bgen;
        if (atomicAdd(&g_bcnt, 1u) == nctas - 1u) {
            g_bcnt = 0;
            __threadfence();
            g_bgen = gen + 1u;
        } else {
            while (g_bgen == gen) __nanosleep(32);
        }
        __threadfence();
    }
    __syncthreads();
}

__device__ __forceinline__ float sigf(float x)  { return __fdividef(1.f, 1.f + __expf(-x)); }
__device__ __forceinline__ float tanhf_fast(float x) { return 1.f - __fdividef(2.f, __expf(2.f * x) + 1.f); }
__device__ __forceinline__ float warp_red(float s) {
#pragma unroll
    for (int o = 16; o; o >>= 1) s += __shfl_down_sync(0xffffffffu, s, o);
    return s;
}
__device__ __forceinline__ float ctx_at(size_t idx) {
    return __half2float(g_h[0][idx]);
}

// ---------------------------------------------------------------------------
// fragment machinery (32m x 32n warp tile, single-pass fp16)
// ---------------------------------------------------------------------------
struct Frag {
    uint32_t ah[2][4], bh[4][2];
};

__device__ __forceinline__ void load_frags(Frag& f, uint32_t Ah, uint32_t Bh,
                                           int ks, int wr, int wc, int lane) {
#pragma unroll
    for (int mt = 0; mt < 2; mt++) {
        int r = wr * 32 + mt * 16 + (lane & 15);
        uint32_t ch = ((uint32_t)((ks * 2 + (lane >> 4)) ^ (r & 7))) << 4;
        LDSM4(f.ah[mt], Ah + r * 128 + ch);
    }
#pragma unroll
    for (int gp = 0; gp < 2; gp++) {
        int rn = (gp * 2 + (lane >> 4)) * 16 + wc * 8 + (lane & 7);
        uint32_t ch = ((uint32_t)((ks * 2 + ((lane >> 3) & 1)) ^ (rn & 7))) << 4;
        LDSM4(&f.bh[gp * 2][0], Bh + rn * 128 + ch);
    }
}

__device__ __forceinline__ void do_mmas(float (&acc)[2][4][4], const Frag& f) {
#pragma unroll
    for (int mt = 0; mt < 2; mt++)
#pragma unroll
        for (int q = 0; q < 4; q++)
            MMA16816(acc[mt][q], f.ah[mt], f.bh[q]);
}

// ---------------------------------------------------------------------------
// init / convert
// ---------------------------------------------------------------------------
__global__ void k_init(const float* __restrict__ bih, const float* __restrict__ bhh) {
    int i = blockIdx.x * blockDim.x + threadIdx.x;
    int n = MPAD * HID;
    __half z = __float2half(0.f);
    for (int j = i; j < n; j += gridDim.x * blockDim.x) {
        g_c[j] = 0.f;
        g_h[0][j] = z; g_h[1][j] = z;
    }
    if (i < 4 * HID) g_bias[i] = bih[i] + bhh[i];
}

__global__ void k_conv_w(const float* __restrict__ Whh, const float* __restrict__ Wih) {
    size_t i = (size_t)blockIdx.x * blockDim.x + threadIdx.x;
    if (i >= (size_t)4096 * KTOT) return;
    int r = (int)(i / KTOT);
    int k = (int)(i % KTOT);
    float v = (k < HID) ? Whh[(size_t)r * HID + k] : Wih[(size_t)r * INPUTD + (k - HID)];
    g_W[i] = __float2half(v);
}

__global__ void k_conv_x(const float* __restrict__ data) {
    size_t i = (size_t)blockIdx.x * blockDim.x + threadIdx.x;
    if (i >= (size_t)T_STEPS * MPAD * INPUTD) return;
    int k = (int)(i % INPUTD);
    int b = (int)((i / INPUTD) % MPAD);
    int t = (int)(i / ((size_t)MPAD * INPUTD));
    float v = (b < BATCH) ? data[((size_t)t * BATCH + b) * INPUTD + k] : 0.f;
    g_x[i] = __float2half(v);
}

// ---------------------------------------------------------------------------
// k_gx: Gx[t] = x_t @ Wih^T for all t.  128 persistent CTAs, weights resident.
// ---------------------------------------------------------------------------
__global__ __launch_bounds__(256, 1) void k_gx() {
    extern __shared__ __align__(128) char smem[];
    const uint32_t sb  = smem_to_u32(smem);
    const uint32_t sbB = sb;
    const uint32_t sbA = sb + 32768;
    const int tid  = threadIdx.x;
    const int lane = tid & 31;
    const int wid  = tid >> 5;
    const int wr   = wid & 3;
    const int wc   = wid >> 2;
    const int n0   = (blockIdx.x & 63) * 16;
    const int m0   = (blockIdx.x >> 6) * 128;
    const int rowq = lane >> 2;
    const int col2 = (lane & 3) * 2;

    // resident B: Wih K-slices (k = 1024 + ci*64), 4 chunks of 8KB
#pragma unroll
    for (int i = tid; i < 2048; i += 256) {
        int ci = i >> 9, r = (i >> 3) & 63, ch = i & 7;
        int wrow = (r >> 4) * HID + n0 + (r & 15);
        size_t off = (size_t)wrow * KTOT + HID + ci * 64 + ch * 8;
        uint32_t dst = sbB + ci * 8192 + r * 128 + (((uint32_t)(ch ^ (r & 7))) << 4);
        CP_ASYNC16(dst, g_W + off);
    }
    CP_COMMIT();

    auto loadA = [&](int lin) {
        int t = lin >> 2, ci = lin & 3;
        uint32_t base = sbA + (lin % 3) * 16384;
#pragma unroll
        for (int i = tid; i < 1024; i += 256) {
            int r = i >> 3, ch = i & 7;
            size_t off = ((size_t)t * MPAD + m0 + r) * INPUTD + ci * 64 + ch * 8;
            uint32_t dst = base + r * 128 + (((uint32_t)(ch ^ (r & 7))) << 4);
            CP_ASYNC16(dst, g_x + off);
        }
        CP_COMMIT();
    };

    loadA(0); loadA(1);
    Frag fr[2];

    for (int t = 0; t < T_STEPS; t++) {
        float acc[2][4][4];
#pragma unroll
        for (int mt = 0; mt < 2; mt++)
#pragma unroll
            for (int q = 0; q < 4; q++)
#pragma unroll
                for (int j = 0; j < 4; j++) acc[mt][q][j] = 0.f;

        for (int ci = 0; ci < 4; ci++) {
            int lin = t * 4 + ci;
            if (lin == T_STEPS * 4 - 1) { CP_WAIT0(); } else { CP_WAIT1(); }
            __syncthreads();
            if (lin + 2 < T_STEPS * 4) loadA(lin + 2);

            const uint32_t Ah = sbA + (lin % 3) * 16384;
            const uint32_t Bh = sbB + ci * 8192;

            load_frags(fr[0], Ah, Bh, 0, wr, wc, lane);
#pragma unroll
            for (int ks = 0; ks < 4; ks++) {
                if (ks < 3) load_frags(fr[(ks + 1) & 1], Ah, Bh, ks + 1, wr, wc, lane);
                do_mmas(acc, fr[ks & 1]);
            }
        }

        float* gx = g_gx + (size_t)t * MPAD * 4096;
#pragma unroll
        for (int mt = 0; mt < 2; mt++)
#pragma unroll
            for (int rp = 0; rp < 2; rp++) {
                int m = m0 + wr * 32 + mt * 16 + rowq + rp * 8;
#pragma unroll
                for (int q = 0; q < 4; q++) {
                    int col = q * 1024 + n0 + wc * 8 + col2;
                    *(float2*)&gx[(size_t)m * 4096 + col] =
                        make_float2(acc[mt][q][rp * 2], acc[mt][q][rp * 2 + 1]);
                }
            }
    }
}

// ---------------------------------------------------------------------------
// k_enc: persistent, 240 LSTM steps, K=1024 (h only), acc init from Gx.
// 128 CTAs x 256 thr (8 warps, 32x32 warp tiles), single-pass fp16.
// ---------------------------------------------------------------------------
__global__ __launch_bounds__(256, 1) void k_enc() {
    extern __shared__ __align__(128) char smem[];
    const uint32_t sb = smem_to_u32(smem);
    const int tid  = threadIdx.x;
    const int lane = tid & 31;
    const int wid  = tid >> 5;
    const int wr   = wid & 3;
    const int wc   = wid >> 2;
    const int n0   = (blockIdx.x & 63) * 16;
    const int m0   = (blockIdx.x >> 6) * 128;
    const int rowq = lane >> 2;
    const int col2 = (lane & 3) * 2;

    for (int t = 0; t < T_STEPS; t++) {
        const int par = t & 1;
        const __half* __restrict__ hIn = g_h[par];

        auto load_chunk = [&](int c) {
            const uint32_t base = sb + (c % 3) * BUFB;
            const int k0 = c * KCH;
#pragma unroll
            for (int i = tid; i < 1024; i += 256) {
                int r = i >> 3, ch = i & 7;
                uint32_t dst = base + r * 128 + (((uint32_t)(ch ^ (r & 7))) << 4);
                size_t off = (size_t)(m0 + r) * HID + k0 + ch * 8;
                CP_ASYNC16(dst, hIn + off);
            }
#pragma unroll
            for (int i = tid; i < 512; i += 256) {
                int r = i >> 3, ch = i & 7;
                uint32_t dst = base + 16384 + r * 128 + (((uint32_t)(ch ^ (r & 7))) << 4);
                int wrow = (r >> 4) * HID + n0 + (r & 15);
                size_t off = (size_t)wrow * KTOT + k0 + ch * 8;
                CP_ASYNC16(dst, g_W + off);
            }
            CP_COMMIT();
        };

        load_chunk(0);
        load_chunk(1);

        // init accumulators from precomputed x @ Wih^T
        float acc[2][4][4];
        {
            const float* gx = g_gx + (size_t)t * MPAD * 4096;
#pragma unroll
            for (int mt = 0; mt < 2; mt++)
#pragma unroll
                for (int rp = 0; rp < 2; rp++) {
                    int m = m0 + wr * 32 + mt * 16 + rowq + rp * 8;
#pragma unroll
                    for (int q = 0; q < 4; q++) {
                        int col = q * 1024 + n0 + wc * 8 + col2;
                        float2 v = *(const float2*)&gx[(size_t)m * 4096 + col];
                        acc[mt][q][rp * 2]     = v.x;
                        acc[mt][q][rp * 2 + 1] = v.y;
                    }
                }
        }

        Frag fr[2];
        for (int c = 0; c < NCH_H; c++) {
            if (c == NCH_H - 1) { CP_WAIT0(); } else { CP_WAIT1(); }
            __syncthreads();
            if (c + 2 < NCH_H) load_chunk(c + 2);

            const uint32_t base = sb + (c % 3) * BUFB;
            const uint32_t Ah = base, Bh = base + 16384;

            load_frags(fr[0], Ah, Bh, 0, wr, wc, lane);
#pragma unroll
            for (int ks = 0; ks < 4; ks++) {
                if (ks < 3) load_frags(fr[(ks + 1) & 1], Ah, Bh, ks + 1, wr, wc, lane);
                do_mmas(acc, fr[ks & 1]);
            }
        }

        // fused LSTM gate epilogue
        __half* __restrict__ hOut = g_h[par ^ 1];
#pragma unroll
        for (int mt = 0; mt < 2; mt++)
#pragma unroll
            for (int rp = 0; rp < 2; rp++) {
                int m = m0 + wr * 32 + mt * 16 + rowq + rp * 8;
                if (m < BATCH) {
                    int n = n0 + wc * 8 + col2;
                    size_t idx = (size_t)m * HID + n;
                    float2 cold = *(float2*)&g_c[idx];
                    float2 bi = *(const float2*)&g_bias[n];
                    float2 bf = *(const float2*)&g_bias[HID + n];
                    float2 bg = *(const float2*)&g_bias[2 * HID + n];
                    float2 bo = *(const float2*)&g_bias[3 * HID + n];
                    float h[2], cn[2];
#pragma unroll
                    for (int j = 0; j < 2; j++) {
                        float gi = acc[mt][0][rp * 2 + j] + (j ? bi.y : bi.x);
                        float gf = acc[mt][1][rp * 2 + j] + (j ? bf.y : bf.x);
                        float gg = acc[mt][2][rp * 2 + j] + (j ? bg.y : bg.x);
                        float go = acc[mt][3][rp * 2 + j] + (j ? bo.y : bo.x);
                        cn[j] = sigf(gf) * (j ? cold.y : cold.x) + sigf(gi) * tanhf_fast(gg);
                        h[j]  = sigf(go) * tanhf_fast(cn[j]);
                    }
                    *(float2*)&g_c[idx] = make_float2(cn[0], cn[1]);
                    *(__half2*)&hOut[idx] =
                        __halves2half2(__float2half(h[0]), __float2half(h[1]));
                }
            }

        gbar(NCTA);
    }
}

// ---------------------------------------------------------------------------
// k_dec: persistent decoder, 128 CTAs x 256 thr, float4 matvecs.
// ---------------------------------------------------------------------------
__global__ __launch_bounds__(256, 1) void k_dec(
    const float* __restrict__ attn_W, const float* __restrict__ attn_b,
    const float* __restrict__ comb_W, const float* __restrict__ comb_b,
    const float* __restrict__ gWih,   const float* __restrict__ gWhh,
    const float* __restrict__ gbih,   const float* __restrict__ gbhh,
    const float* __restrict__ out_W,  const float* __restrict__ out_b,
    float* __restrict__ outp)
{
    const int tid  = threadIdx.x;
    const int bid  = blockIdx.x;
    const int lane = tid & 31;
    const int warp = tid >> 5;
    const int gw   = bid * 8 + warp;   // 0..1023

    if (bid == 0) {
        for (int i = tid; i < HID; i += 256) {
            float v = ctx_at((size_t)(BATCH - 1) * HID + i);
            g_hdec[i] = v;
            g_v[OUTD + i] = v;
        }
        if (tid < OUTD) { g_u[tid] = 0.125f; g_v[tid] = 0.125f; g_v2[tid] = 0.125f; }
    }
    gbar(NCTA);

    for (int step = 0; step < NSTEPS; step++) {
        // ph1: attention scores
        if (gw < WW) {
            const float4* row = (const float4*)(attn_W + (size_t)gw * (HID + OUTD));
            const float4* v   = (const float4*)g_v;
            float s = 0.f;
            for (int k = lane; k < (HID + OUTD) / 4; k += 32) {
                float4 w = row[k], x = v[k];
                s += w.x * x.x + w.y * x.y + w.z * x.z + w.w * x.w;
            }
            s = warp_red(s);
            if (!lane) g_sc[gw] = s + attn_b[gw];
        }
        gbar(NCTA);

        // ph2: softmax (CTA 0)
        if (bid == 0) {
            __shared__ float rbuf[8];
            float x = (tid < WW) ? g_sc[tid] : -1e30f;
            float mx = x;
#pragma unroll
            for (int o = 16; o; o >>= 1) mx = fmaxf(mx, __shfl_xor_sync(0xffffffffu, mx, o));
            if (!lane) rbuf[warp] = mx;
            __syncthreads();
            float bm = rbuf[0];
#pragma unroll
            for (int i = 1; i < 8; i++) bm = fmaxf(bm, rbuf[i]);
            float e = (tid < WW) ? __expf(x - bm) : 0.f;
            float sm = e;
#pragma unroll
            for (int o = 16; o; o >>= 1) sm += __shfl_xor_sync(0xffffffffu, sm, o);
            __syncthreads();
            if (!lane) rbuf[warp] = sm;
            __syncthreads();
            float tot = 0.f;
#pragma unroll
            for (int i = 0; i < 8; i++) tot += rbuf[i];
            if (tid < WW) g_aw[tid] = e / tot;
        }
        gbar(NCTA);

        // ph3: applied = aw @ ctx -> g_v2[OUTD + n]
        {
            int n = gw;
            float s = 0.f;
            for (int j = lane; j < WW; j += 32) s += g_aw[j] * ctx_at((size_t)j * HID + n);
            s = warp_red(s);
            if (!lane) g_v2[OUTD + n] = s;
        }
        gbar(NCTA);

        // ph4: comb = relu(comb_W @ v2 + b)
        {
            const float4* row = (const float4*)(comb_W + (size_t)gw * (HID + OUTD));
            const float4* v   = (const float4*)g_v2;
            float s = 0.f;
            for (int k = lane; k < (HID + OUTD) / 4; k += 32) {
                float4 w = row[k], x = v[k];
                s += w.x * x.x + w.y * x.y + w.z * x.z + w.w * x.w;
            }
            s = warp_red(s);
            if (!lane) g_comb[gw] = fmaxf(s + comb_b[gw], 0.f);
        }
        gbar(NCTA);

        // ph5: gi / gh (6144 rows over 1024 warps)
        for (int rr = gw; rr < 6 * HID; rr += 1024) {
            const float4* row;
            const float4* v;
            if (rr < 3 * HID) {
                row = (const float4*)(gWih + (size_t)rr * HID);
                v = (const float4*)g_comb;
            } else {
                row = (const float4*)(gWhh + (size_t)(rr - 3 * HID) * HID);
                v = (const float4*)g_hdec;
            }
            float s = 0.f;
            for (int k = lane; k < HID / 4; k += 32) {
                float4 w = row[k], x = v[k];
                s += w.x * x.x + w.y * x.y + w.z * x.z + w.w * x.w;
            }
            s = warp_red(s);
            if (!lane) {
                if (rr < 3 * HID) g_gi[rr] = s + gbih[rr];
                else              g_gh[rr - 3 * HID] = s + gbhh[rr - 3 * HID];
            }
        }
        gbar(NCTA);

        // ph6: gate update + output head + next-step vector (CTA 0)
        if (bid == 0) {
            for (int n = tid; n < HID; n += 256) {
                float r  = sigf(g_gi[n] + g_gh[n]);
                float z  = sigf(g_gi[HID + n] + g_gh[HID + n]);
                float nn = tanhf_fast(g_gi[2 * HID + n] + r * g_gh[2 * HID + n]);
                g_hdec[n] = (1.f - z) * nn + z * g_hdec[n];
            }
            __syncthreads();
            __shared__ float lg[OUTD];
            if (warp < OUTD) {
                const float4* row = (const float4*)(out_W + (size_t)warp * HID);
                const float4* v   = (const float4*)g_hdec;
                float s = 0.f;
                for (int k = lane; k < HID / 4; k += 32) {
                    float4 w = row[k], x = v[k];
                    s += w.x * x.x + w.y * x.y + w.z * x.z + w.w * x.w;
                }
                s = warp_red(s);
                if (!lane) lg[warp] = s + out_b[warp];
            }
            __syncthreads();
            if (tid == 0) {
                float mx = -1e30f;
#pragma unroll
                for (int i = 0; i < OUTD; i++) mx = fmaxf(mx, lg[i]);
                float sum = 0.f;
#pragma unroll
                for (int i = 0; i < OUTD; i++) sum += __expf(lg[i] - mx);
                float lse = mx + __logf(sum);
#pragma unroll
                for (int i = 0; i < OUTD; i++) {
                    float lp = lg[i] - lse;
                    outp[step * OUTD + i] = lp;
                    g_u[i] = lp;
                }
            }
            __syncthreads();
            for (int i = tid; i < HID; i += 256) g_v[OUTD + i] = g_hdec[i];
            if (tid < OUTD) { float u = g_u[tid]; g_v[tid] = u; g_v2[tid] = u; }
        }
        gbar(NCTA);
    }
}

// ---------------------------------------------------------------------------
// launch
// ---------------------------------------------------------------------------
extern "C" void kernel_launch(void* const* d_in, const int* in_sizes, int n_in,
                              void* d_out, int out_size) {
    const float* data     = (const float*)d_in[0];
    const float* enc_Wih  = (const float*)d_in[1];
    const float* enc_Whh  = (const float*)d_in[2];
    const float* enc_bih  = (const float*)d_in[3];
    const float* enc_bhh  = (const float*)d_in[4];
    const float* attn_W   = (const float*)d_in[5];
    const float* attn_b   = (const float*)d_in[6];
    const float* comb_W   = (const float*)d_in[7];
    const float* comb_b   = (const float*)d_in[8];
    const float* gru_Wih  = (const float*)d_in[9];
    const float* gru_Whh  = (const float*)d_in[10];
    const float* gru_bih  = (const float*)d_in[11];
    const float* gru_bhh  = (const float*)d_in[12];
    const float* out_W    = (const float*)d_in[13];
    const float* out_b    = (const float*)d_in[14];
    float* out = (float*)d_out;

    cudaFuncSetAttribute(k_enc, cudaFuncAttributeMaxDynamicSharedMemorySize, SMEMB);
    cudaFuncSetAttribute(k_gx,  cudaFuncAttributeMaxDynamicSharedMemorySize, GXSMEM);

    k_init<<<1024, 256>>>(enc_bih, enc_bhh);
    k_conv_w<<<(4096 * KTOT + 255) / 256, 256>>>(enc_Whh, enc_Wih);
    k_conv_x<<<(T_STEPS * MPAD * INPUTD + 255) / 256, 256>>>(data);

    k_gx<<<NCTA, 256, GXSMEM>>>();
    k_enc<<<NCTA, 256, SMEMB>>>();

    k_dec<<<NCTA, 256>>>(attn_W, attn_b, comb_W, comb_b,
                         gru_Wih, gru_Whh, gru_bih, gru_bhh,
                         out_W, out_b, out);
}

// round 10
// speedup vs baseline: 1.6508x; 1.0044x over previous
#include <cuda_runtime.h>
#include <cuda_fp16.h>
#include <math.h>
#include <cstdint>

#define T_STEPS 240
#define BATCH   240
#define MPAD    256
#define INPUTD  256
#define HID     1024
#define NSTEPS  30
#define OUTD    8
#define WW      240
#define KTOT    1280
#define KCH     64
#define NCH_H   16
#define NCTA    128
#define NCTA_D  64

// encoder smem: W resident 16 chunks x 8KB = 128KB, A 3 x 16KB
#define SMW     131072
#define SMEMB   (SMW + 3 * 16384)
// gx smem: B resident 32KB + A 3x16KB
#define GXSMEM  (32768 + 3 * 16384)

// ---------------------------------------------------------------------------
// helpers
// ---------------------------------------------------------------------------
__device__ __forceinline__ uint32_t smem_to_u32(const void* p) {
    uint32_t a;
    asm("{ .reg .u64 t; cvta.to.shared.u64 t, %1; cvt.u32.u64 %0, t; }" : "=r"(a) : "l"(p));
    return a;
}

#define CP_ASYNC16(dst, src) \
    asm volatile("cp.async.cg.shared.global [%0], [%1], 16;" \
                 :: "r"(dst), "l"(__cvta_generic_to_global(src)))
#define CP_COMMIT() asm volatile("cp.async.commit_group;" ::: "memory")
#define CP_WAIT1()  asm volatile("cp.async.wait_group 1;" ::: "memory")
#define CP_WAIT0()  asm volatile("cp.async.wait_group 0;" ::: "memory")

#define LDSM4(r, addr) \
    asm volatile("ldmatrix.sync.aligned.m8n8.x4.shared.b16 {%0,%1,%2,%3}, [%4];" \
                 : "=r"((r)[0]), "=r"((r)[1]), "=r"((r)[2]), "=r"((r)[3]) : "r"(addr))

#define MMA16816(d, a, b) \
    asm volatile("mma.sync.aligned.m16n8k16.row.col.f32.f16.f16.f32 " \
                 "{%0,%1,%2,%3}, {%4,%5,%6,%7}, {%8,%9}, {%0,%1,%2,%3};" \
                 : "+f"((d)[0]), "+f"((d)[1]), "+f"((d)[2]), "+f"((d)[3]) \
                 : "r"((a)[0]), "r"((a)[1]), "r"((a)[2]), "r"((a)[3]), \
                   "r"((b)[0]), "r"((b)[1]))

// ---------------------------------------------------------------------------
// device scratch
// ---------------------------------------------------------------------------
__device__ __align__(256) __half g_W[4096 * KTOT];
__device__ __align__(256) __half g_x[(size_t)T_STEPS * MPAD * INPUTD];
__device__ __align__(256) __half g_h[2][MPAD * HID];
__device__ __align__(256) __half g_gx16[(size_t)T_STEPS * MPAD * 4096];  // x @ Wih^T, fp16
__device__ __align__(256) float g_c[MPAD * HID];
__device__ __align__(16) float g_bias[4 * HID];

// decoder fp16 weights
__device__ __align__(256) __half g_attnWh[WW * HID];
__device__ __align__(256) __half g_combWh[HID * HID];
__device__ __align__(256) __half g_gWih16[3 * HID * HID];
__device__ __align__(256) __half g_gWhh16[3 * HID * HID];
__device__ __align__(256) __half g_ctxT[(size_t)HID * WW];

__device__ __align__(16) float g_u[OUTD];
__device__ __align__(16) float g_hdec[HID];
__device__ __align__(16) float g_comb[HID];
__device__ __align__(16) float g_gi[3 * HID];
__device__ __align__(16) float g_gh[3 * HID];
__device__ __align__(16) float g_v2[HID + OUTD];   // [u; applied]
__device__ float g_sch[WW];

__device__ unsigned g_bcnt = 0;
__device__ volatile unsigned g_bgen = 0;
__device__ unsigned g_bcH[2] = {0, 0};
__device__ volatile unsigned g_bgH[2] = {0, 0};

__device__ __forceinline__ void gbar(unsigned nctas) {
    __syncthreads();
    if (threadIdx.x == 0) {
        __threadfence();
        unsigned gen = g_bgen;
        if (atomicAdd(&g_bcnt, 1u) == nctas - 1u) {
            g_bcnt = 0;
            __threadfence();
            g_bgen = gen + 1u;
        } else {
            while (g_bgen == gen) __nanosleep(32);
        }
        __threadfence();
    }
    __syncthreads();
}

__device__ __forceinline__ void gbarH(int h, unsigned nctas) {
    __syncthreads();
    if (threadIdx.x == 0) {
        __threadfence();
        unsigned gen = g_bgH[h];
        if (atomicAdd(&g_bcH[h], 1u) == nctas - 1u) {
            g_bcH[h] = 0;
            __threadfence();
            g_bgH[h] = gen + 1u;
        } else {
            while (g_bgH[h] == gen) __nanosleep(32);
        }
        __threadfence();
    }
    __syncthreads();
}

__device__ __forceinline__ float sigf(float x)  { return __fdividef(1.f, 1.f + __expf(-x)); }
__device__ __forceinline__ float tanhf_fast(float x) { return 1.f - __fdividef(2.f, __expf(2.f * x) + 1.f); }
__device__ __forceinline__ float warp_red(float s) {
#pragma unroll
    for (int o = 16; o; o >>= 1) s += __shfl_down_sync(0xffffffffu, s, o);
    return s;
}

// fp16-weight x fp32-vector dot, length 1024, lane-strided
__device__ __forceinline__ float dot1024(const __half* __restrict__ w,
                                         const float* __restrict__ v, int lane) {
    float s = 0.f;
    const uint4* w4 = (const uint4*)w;
#pragma unroll
    for (int k = lane; k < 128; k += 32) {
        uint4 u = w4[k];
        const float4* vv = (const float4*)(v + (k << 3));
        float4 va = vv[0], vb = vv[1];
        float2 f0 = __half22float2(*(__half2*)&u.x);
        float2 f1 = __half22float2(*(__half2*)&u.y);
        float2 f2 = __half22float2(*(__half2*)&u.z);
        float2 f3 = __half22float2(*(__half2*)&u.w);
        s += f0.x * va.x + f0.y * va.y + f1.x * va.z + f1.y * va.w
           + f2.x * vb.x + f2.y * vb.y + f3.x * vb.z + f3.y * vb.w;
    }
    return s;
}

// ---------------------------------------------------------------------------
// fragment machinery (32m x 32n warp tile, single-pass fp16)
// ---------------------------------------------------------------------------
struct Frag {
    uint32_t ah[2][4], bh[4][2];
};

__device__ __forceinline__ void load_frags(Frag& f, uint32_t Ah, uint32_t Bh,
                                           int ks, int wr, int wc, int lane) {
#pragma unroll
    for (int mt = 0; mt < 2; mt++) {
        int r = wr * 32 + mt * 16 + (lane & 15);
        uint32_t ch = ((uint32_t)((ks * 2 + (lane >> 4)) ^ (r & 7))) << 4;
        LDSM4(f.ah[mt], Ah + r * 128 + ch);
    }
#pragma unroll
    for (int gp = 0; gp < 2; gp++) {
        int rn = (gp * 2 + (lane >> 4)) * 16 + wc * 8 + (lane & 7);
        uint32_t ch = ((uint32_t)((ks * 2 + ((lane >> 3) & 1)) ^ (rn & 7))) << 4;
        LDSM4(&f.bh[gp * 2][0], Bh + rn * 128 + ch);
    }
}

__device__ __forceinline__ void do_mmas(float (&acc)[2][4][4], const Frag& f) {
#pragma unroll
    for (int mt = 0; mt < 2; mt++)
#pragma unroll
        for (int q = 0; q < 4; q++)
            MMA16816(acc[mt][q], f.ah[mt], f.bh[q]);
}

// ---------------------------------------------------------------------------
// init / convert
// ---------------------------------------------------------------------------
__global__ void k_init(const float* __restrict__ bih, const float* __restrict__ bhh) {
    int i = blockIdx.x * blockDim.x + threadIdx.x;
    int n = MPAD * HID;
    __half z = __float2half(0.f);
    for (int j = i; j < n; j += gridDim.x * blockDim.x) {
        g_c[j] = 0.f;
        g_h[0][j] = z; g_h[1][j] = z;
    }
    if (i < 4 * HID) g_bias[i] = bih[i] + bhh[i];
}

__global__ void k_conv_w(const float* __restrict__ Whh, const float* __restrict__ Wih) {
    size_t i = (size_t)blockIdx.x * blockDim.x + threadIdx.x;
    if (i >= (size_t)4096 * KTOT) return;
    int r = (int)(i / KTOT);
    int k = (int)(i % KTOT);
    float v = (k < HID) ? Whh[(size_t)r * HID + k] : Wih[(size_t)r * INPUTD + (k - HID)];
    g_W[i] = __float2half(v);
}

__global__ void k_conv_x(const float* __restrict__ data) {
    size_t i = (size_t)blockIdx.x * blockDim.x + threadIdx.x;
    if (i >= (size_t)T_STEPS * MPAD * INPUTD) return;
    int k = (int)(i % INPUTD);
    int b = (int)((i / INPUTD) % MPAD);
    int t = (int)(i / ((size_t)MPAD * INPUTD));
    float v = (b < BATCH) ? data[((size_t)t * BATCH + b) * INPUTD + k] : 0.f;
    g_x[i] = __float2half(v);
}

__global__ void k_conv_dec(const float* __restrict__ attn_W, const float* __restrict__ comb_W,
                           const float* __restrict__ gWih, const float* __restrict__ gWhh) {
    size_t i = (size_t)blockIdx.x * blockDim.x + threadIdx.x;
    const size_t nA = (size_t)WW * HID;
    const size_t nC = (size_t)HID * HID;
    const size_t nG = (size_t)3 * HID * HID;
    if (i < nA) {
        size_t j = i / HID, k = i % HID;
        g_attnWh[i] = __float2half(attn_W[j * (HID + OUTD) + OUTD + k]);
        return;
    }
    i -= nA;
    if (i < nC) {
        size_t r = i / HID, k = i % HID;
        g_combWh[i] = __float2half(comb_W[r * (HID + OUTD) + OUTD + k]);
        return;
    }
    i -= nC;
    if (i < nG) { g_gWih16[i] = __float2half(gWih[i]); return; }
    i -= nG;
    if (i < nG) { g_gWhh16[i] = __float2half(gWhh[i]); return; }
}

// ---------------------------------------------------------------------------
// k_gx: Gx[t] = x_t @ Wih^T for all t (fp16 output). 128 persistent CTAs.
// ---------------------------------------------------------------------------
__global__ __launch_bounds__(256, 1) void k_gx() {
    extern __shared__ __align__(128) char smem[];
    const uint32_t sb  = smem_to_u32(smem);
    const uint32_t sbB = sb;
    const uint32_t sbA = sb + 32768;
    const int tid  = threadIdx.x;
    const int lane = tid & 31;
    const int wid  = tid >> 5;
    const int wr   = wid & 3;
    const int wc   = wid >> 2;
    const int n0   = (blockIdx.x & 63) * 16;
    const int m0   = (blockIdx.x >> 6) * 128;
    const int rowq = lane >> 2;
    const int col2 = (lane & 3) * 2;

#pragma unroll
    for (int i = tid; i < 2048; i += 256) {
        int ci = i >> 9, r = (i >> 3) & 63, ch = i & 7;
        int wrow = (r >> 4) * HID + n0 + (r & 15);
        size_t off = (size_t)wrow * KTOT + HID + ci * 64 + ch * 8;
        uint32_t dst = sbB + ci * 8192 + r * 128 + (((uint32_t)(ch ^ (r & 7))) << 4);
        CP_ASYNC16(dst, g_W + off);
    }
    CP_COMMIT();

    auto loadA = [&](int lin) {
        int t = lin >> 2, ci = lin & 3;
        uint32_t base = sbA + (lin % 3) * 16384;
#pragma unroll
        for (int i = tid; i < 1024; i += 256) {
            int r = i >> 3, ch = i & 7;
            size_t off = ((size_t)t * MPAD + m0 + r) * INPUTD + ci * 64 + ch * 8;
            uint32_t dst = base + r * 128 + (((uint32_t)(ch ^ (r & 7))) << 4);
            CP_ASYNC16(dst, g_x + off);
        }
        CP_COMMIT();
    };

    loadA(0); loadA(1);
    Frag fr[2];

    for (int t = 0; t < T_STEPS; t++) {
        float acc[2][4][4];
#pragma unroll
        for (int mt = 0; mt < 2; mt++)
#pragma unroll
            for (int q = 0; q < 4; q++)
#pragma unroll
                for (int j = 0; j < 4; j++) acc[mt][q][j] = 0.f;

        for (int ci = 0; ci < 4; ci++) {
            int lin = t * 4 + ci;
            if (lin == T_STEPS * 4 - 1) { CP_WAIT0(); } else { CP_WAIT1(); }
            __syncthreads();
            if (lin + 2 < T_STEPS * 4) loadA(lin + 2);

            const uint32_t Ah = sbA + (lin % 3) * 16384;
            const uint32_t Bh = sbB + ci * 8192;

            load_frags(fr[0], Ah, Bh, 0, wr, wc, lane);
#pragma unroll
            for (int ks = 0; ks < 4; ks++) {
                if (ks < 3) load_frags(fr[(ks + 1) & 1], Ah, Bh, ks + 1, wr, wc, lane);
                do_mmas(acc, fr[ks & 1]);
            }
        }

        __half* gx = g_gx16 + (size_t)t * MPAD * 4096;
#pragma unroll
        for (int mt = 0; mt < 2; mt++)
#pragma unroll
            for (int rp = 0; rp < 2; rp++) {
                int m = m0 + wr * 32 + mt * 16 + rowq + rp * 8;
#pragma unroll
                for (int q = 0; q < 4; q++) {
                    int col = q * 1024 + n0 + wc * 8 + col2;
                    *(__half2*)&gx[(size_t)m * 4096 + col] =
                        __floats2half2_rn(acc[mt][q][rp * 2], acc[mt][q][rp * 2 + 1]);
                }
            }
    }
}

// ---------------------------------------------------------------------------
// k_enc: persistent, 240 LSTM steps, weights RESIDENT in smem (128KB).
// 128 CTAs x 256 thr; per-m-half barriers (64 CTAs each).
// ---------------------------------------------------------------------------
__global__ __launch_bounds__(256, 1) void k_enc() {
    extern __shared__ __align__(128) char smem[];
    const uint32_t sb  = smem_to_u32(smem);
    const uint32_t sbW = sb;
    const uint32_t sbA = sb + SMW;
    const int tid  = threadIdx.x;
    const int lane = tid & 31;
    const int wid  = tid >> 5;
    const int wr   = wid & 3;
    const int wc   = wid >> 2;
    const int n0   = (blockIdx.x & 63) * 16;
    const int mh   = blockIdx.x >> 6;
    const int m0   = mh * 128;
    const int rowq = lane >> 2;
    const int col2 = (lane & 3) * 2;

    // resident W: 16 chunks x (64 rows x 64 k) = 128 KB
#pragma unroll
    for (int i = tid; i < 8192; i += 256) {
        int ci = i >> 9, r = (i >> 3) & 63, ch = i & 7;
        int wrow = (r >> 4) * HID + n0 + (r & 15);
        size_t off = (size_t)wrow * KTOT + ci * 64 + ch * 8;
        uint32_t dst = sbW + ci * 8192 + r * 128 + (((uint32_t)(ch ^ (r & 7))) << 4);
        CP_ASYNC16(dst, g_W + off);
    }
    CP_COMMIT();

    for (int t = 0; t < T_STEPS; t++) {
        const int par = t & 1;
        const __half* __restrict__ hIn = g_h[par];

        auto loadA = [&](int c) {
            const uint32_t base = sbA + (c % 3) * 16384;
            const int k0 = c * KCH;
#pragma unroll
            for (int i = tid; i < 1024; i += 256) {
                int r = i >> 3, ch = i & 7;
                uint32_t dst = base + r * 128 + (((uint32_t)(ch ^ (r & 7))) << 4);
                size_t off = (size_t)(m0 + r) * HID + k0 + ch * 8;
                CP_ASYNC16(dst, hIn + off);
            }
            CP_COMMIT();
        };

        loadA(0);
        loadA(1);

        // init accumulators from precomputed x @ Wih^T (fp16)
        float acc[2][4][4];
        {
            const __half* gx = g_gx16 + (size_t)t * MPAD * 4096;
#pragma unroll
            for (int mt = 0; mt < 2; mt++)
#pragma unroll
                for (int rp = 0; rp < 2; rp++) {
                    int m = m0 + wr * 32 + mt * 16 + rowq + rp * 8;
#pragma unroll
                    for (int q = 0; q < 4; q++) {
                        int col = q * 1024 + n0 + wc * 8 + col2;
                        float2 v = __half22float2(*(const __half2*)&gx[(size_t)m * 4096 + col]);
                        acc[mt][q][rp * 2]     = v.x;
                        acc[mt][q][rp * 2 + 1] = v.y;
                    }
                }
        }

        Frag fr[2];
        for (int c = 0; c < NCH_H; c++) {
            if (c == NCH_H - 1) { CP_WAIT0(); } else { CP_WAIT1(); }
            __syncthreads();
            if (c + 2 < NCH_H) loadA(c + 2);

            const uint32_t Ah = sbA + (c % 3) * 16384;
            const uint32_t Bh = sbW + c * 8192;

            load_frags(fr[0], Ah, Bh, 0, wr, wc, lane);
#pragma unroll
            for (int ks = 0; ks < 4; ks++) {
                if (ks < 3) load_frags(fr[(ks + 1) & 1], Ah, Bh, ks + 1, wr, wc, lane);
                do_mmas(acc, fr[ks & 1]);
            }
        }

        // fused LSTM gate epilogue
        __half* __restrict__ hOut = g_h[par ^ 1];
#pragma unroll
        for (int mt = 0; mt < 2; mt++)
#pragma unroll
            for (int rp = 0; rp < 2; rp++) {
                int m = m0 + wr * 32 + mt * 16 + rowq + rp * 8;
                if (m < BATCH) {
                    int n = n0 + wc * 8 + col2;
                    size_t idx = (size_t)m * HID + n;
                    float2 cold = *(float2*)&g_c[idx];
                    float2 bi = *(const float2*)&g_bias[n];
                    float2 bf = *(const float2*)&g_bias[HID + n];
                    float2 bg = *(const float2*)&g_bias[2 * HID + n];
                    float2 bo = *(const float2*)&g_bias[3 * HID + n];
                    float h[2], cn[2];
#pragma unroll
                    for (int j = 0; j < 2; j++) {
                        float gi = acc[mt][0][rp * 2 + j] + (j ? bi.y : bi.x);
                        float gf = acc[mt][1][rp * 2 + j] + (j ? bf.y : bf.x);
                        float gg = acc[mt][2][rp * 2 + j] + (j ? bg.y : bg.x);
                        float go = acc[mt][3][rp * 2 + j] + (j ? bo.y : bo.x);
                        cn[j] = sigf(gf) * (j ? cold.y : cold.x) + sigf(gi) * tanhf_fast(gg);
                        h[j]  = sigf(go) * tanhf_fast(cn[j]);
                    }
                    *(float2*)&g_c[idx] = make_float2(cn[0], cn[1]);
                    *(__half2*)&hOut[idx] =
                        __halves2half2(__float2half(h[0]), __float2half(h[1]));
                }
            }

        gbarH(mh, 64);
    }
}

// ---------------------------------------------------------------------------
// k_dec: persistent decoder, 64 CTAs x 256 thr, 5 barriers/step, fp16 weights.
// ---------------------------------------------------------------------------
__global__ __launch_bounds__(256, 1) void k_dec(
    const float* __restrict__ attn_W, const float* __restrict__ attn_b,
    const float* __restrict__ comb_W, const float* __restrict__ comb_b,
    const float* __restrict__ gbih,   const float* __restrict__ gbhh,
    const float* __restrict__ out_W,  const float* __restrict__ out_b,
    float* __restrict__ outp)
{
    __shared__ float s_aw[WW];
    __shared__ float rbuf[8];
    __shared__ float lg[OUTD];

    const int tid  = threadIdx.x;
    const int bid  = blockIdx.x;
    const int lane = tid & 31;
    const int warp = tid >> 5;
    const int gw   = bid * 8 + warp;   // 0..511
    const int gt   = bid * 256 + tid;  // 0..16383

    // init: hdec, u, transposed ctx
    if (gt < HID) g_hdec[gt] = __half2float(g_h[0][(size_t)(BATCH - 1) * HID + gt]);
    if (gt < OUTD) g_u[gt] = 0.125f;
    for (size_t i = gt; i < (size_t)WW * HID; i += NCTA_D * 256) {
        size_t j = i / HID, n = i % HID;
        g_ctxT[n * WW + j] = g_h[0][j * HID + n];
    }
    gbar(NCTA_D);

    auto out_head = [&](int sidx) {
        if (warp < OUTD) {
            const float4* row = (const float4*)(out_W + (size_t)warp * HID);
            const float4* v   = (const float4*)g_hdec;
            float s = 0.f;
            for (int k = lane; k < HID / 4; k += 32) {
                float4 w = row[k], x = v[k];
                s += w.x * x.x + w.y * x.y + w.z * x.z + w.w * x.w;
            }
            s = warp_red(s);
            if (!lane) lg[warp] = s + out_b[warp];
        }
        __syncthreads();
        if (tid == 0) {
            float mx = -1e30f;
#pragma unroll
            for (int i = 0; i < OUTD; i++) mx = fmaxf(mx, lg[i]);
            float sum = 0.f;
#pragma unroll
            for (int i = 0; i < OUTD; i++) sum += __expf(lg[i] - mx);
            float lse = mx + __logf(sum);
#pragma unroll
            for (int i = 0; i < OUTD; i++) {
                float lp = lg[i] - lse;
                outp[sidx * OUTD + i] = lp;
                g_u[i] = lp;
            }
        }
        __syncthreads();
    };

    for (int s = 0; s < NSTEPS; s++) {
        // P1: CTA0 -> prev-step output head (writes u); others -> attn score_h
        if (bid == 0) {
            if (s > 0) out_head(s - 1);
        } else {
            int j = gw - 8;
            if (j < WW) {
                float x = dot1024(g_attnWh + (size_t)j * HID, g_hdec, lane);
                x = warp_red(x);
                if (!lane) g_sch[j] = x;
            }
        }
        gbar(NCTA_D);

        // P2: per-CTA redundant softmax + applied columns
        {
            float x;
            if (tid < WW) {
                float su = 0.f;
#pragma unroll
                for (int k = 0; k < OUTD; k++)
                    su += g_u[k] * attn_W[(size_t)tid * (HID + OUTD) + k];
                x = g_sch[tid] + su + attn_b[tid];
            } else x = -1e30f;
            float mx = x;
#pragma unroll
            for (int o = 16; o; o >>= 1) mx = fmaxf(mx, __shfl_xor_sync(0xffffffffu, mx, o));
            if (!lane) rbuf[warp] = mx;
            __syncthreads();
            float bm = rbuf[0];
#pragma unroll
            for (int i = 1; i < 8; i++) bm = fmaxf(bm, rbuf[i]);
            float e = (tid < WW) ? __expf(x - bm) : 0.f;
            float sm = e;
#pragma unroll
            for (int o = 16; o; o >>= 1) sm += __shfl_xor_sync(0xffffffffu, sm, o);
            __syncthreads();
            if (!lane) rbuf[warp] = sm;
            __syncthreads();
            float tot = 0.f;
#pragma unroll
            for (int i = 0; i < 8; i++) tot += rbuf[i];
            if (tid < WW) s_aw[tid] = e / tot;
            __syncthreads();
#pragma unroll
            for (int rep = 0; rep < 2; rep++) {
                int n = bid * 8 + warp + rep * 512;
                const __half* ct = g_ctxT + (size_t)n * WW;
                float a = 0.f;
                for (int j = lane; j < WW; j += 32) a += s_aw[j] * __half2float(ct[j]);
                a = warp_red(a);
                if (!lane) g_v2[OUTD + n] = a;
            }
            if (bid == 0 && tid < OUTD) g_v2[tid] = g_u[tid];
        }
        gbar(NCTA_D);

        // P3: comb = relu(comb_W @ [u; applied] + b)
#pragma unroll
        for (int rep = 0; rep < 2; rep++) {
            int r = gw + rep * 512;
            float x = dot1024(g_combWh + (size_t)r * HID, g_v2 + OUTD, lane);
            x = warp_red(x);
            if (!lane) {
                float su = 0.f;
#pragma unroll
                for (int k = 0; k < OUTD; k++)
                    su += comb_W[(size_t)r * (HID + OUTD) + k] * g_v2[k];
                g_comb[r] = fmaxf(x + su + comb_b[r], 0.f);
            }
        }
        gbar(NCTA_D);

        // P4: gi / gh (6144 rows over 512 warps)
        for (int rr = gw; rr < 6 * HID; rr += 512) {
            float x;
            if (rr < 3 * HID) x = dot1024(g_gWih16 + (size_t)rr * HID, g_comb, lane);
            else              x = dot1024(g_gWhh16 + (size_t)(rr - 3 * HID) * HID, g_hdec, lane);
            x = warp_red(x);
            if (!lane) {
                if (rr < 3 * HID) g_gi[rr] = x + gbih[rr];
                else              g_gh[rr - 3 * HID] = x + gbhh[rr - 3 * HID];
            }
        }
        gbar(NCTA_D);

        // P5: distributed hdec update
        if (tid < 16) {
            int n = bid * 16 + tid;
            float r  = sigf(g_gi[n] + g_gh[n]);
            float z  = sigf(g_gi[HID + n] + g_gh[HID + n]);
            float nn = tanhf_fast(g_gi[2 * HID + n] + r * g_gh[2 * HID + n]);
            g_hdec[n] = (1.f - z) * nn + z * g_hdec[n];
        }
        gbar(NCTA_D);
    }

    // final output head
    if (bid == 0) out_head(NSTEPS - 1);
}

// ---------------------------------------------------------------------------
// launch
// ---------------------------------------------------------------------------
extern "C" void kernel_launch(void* const* d_in, const int* in_sizes, int n_in,
                              void* d_out, int out_size) {
    const float* data     = (const float*)d_in[0];
    const float* enc_Wih  = (const float*)d_in[1];
    const float* enc_Whh  = (const float*)d_in[2];
    const float* enc_bih  = (const float*)d_in[3];
    const float* enc_bhh  = (const float*)d_in[4];
    const float* attn_W   = (const float*)d_in[5];
    const float* attn_b   = (const float*)d_in[6];
    const float* comb_W   = (const float*)d_in[7];
    const float* comb_b   = (const float*)d_in[8];
    const float* gru_Wih  = (const float*)d_in[9];
    const float* gru_Whh  = (const float*)d_in[10];
    const float* gru_bih  = (const float*)d_in[11];
    const float* gru_bhh  = (const float*)d_in[12];
    const float* out_W    = (const float*)d_in[13];
    const float* out_b    = (const float*)d_in[14];
    float* out = (float*)d_out;

    cudaFuncSetAttribute(k_enc, cudaFuncAttributeMaxDynamicSharedMemorySize, SMEMB);
    cudaFuncSetAttribute(k_gx,  cudaFuncAttributeMaxDynamicSharedMemorySize, GXSMEM);

    k_init<<<1024, 256>>>(enc_bih, enc_bhh);
    k_conv_w<<<(4096 * KTOT + 255) / 256, 256>>>(enc_Whh, enc_Wih);
    k_conv_x<<<(T_STEPS * MPAD * INPUTD + 255) / 256, 256>>>(data);
    {
        size_t ntot = (size_t)WW * HID + (size_t)HID * HID + 2 * (size_t)3 * HID * HID;
        k_conv_dec<<<(int)((ntot + 255) / 256), 256>>>(attn_W, comb_W, gru_Wih, gru_Whh);
    }

    k_gx<<<NCTA, 256, GXSMEM>>>();
    k_enc<<<NCTA, 256, SMEMB>>>();

    k_dec<<<NCTA_D, 256>>>(attn_W, attn_b, comb_W, comb_b,
                           gru_bih, gru_bhh, out_W, out_b, out);
}

// round 11
// speedup vs baseline: 1.9187x; 1.1623x over previous
#include <cuda_runtime.h>
#include <cuda_fp16.h>
#include <math.h>
#include <cstdint>

#define T_STEPS 240
#define BATCH   240
#define MPAD    256
#define INPUTD  256
#define HID     1024
#define NSTEPS  30
#define OUTD    8
#define WW      240
#define KTOT    1280
#define KCH     64
#define NCTA    128
#define NCTA_D  64

// encoder smem: W resident 20 chunks x 8KB = 160KB, A ring 3 x 16KB
#define SMW     163840
#define SMEMB   (SMW + 3 * 16384)

// ---------------------------------------------------------------------------
// helpers
// ---------------------------------------------------------------------------
__device__ __forceinline__ uint32_t smem_to_u32(const void* p) {
    uint32_t a;
    asm("{ .reg .u64 t; cvta.to.shared.u64 t, %1; cvt.u32.u64 %0, t; }" : "=r"(a) : "l"(p));
    return a;
}

#define CP_ASYNC16(dst, src) \
    asm volatile("cp.async.cg.shared.global [%0], [%1], 16;" \
                 :: "r"(dst), "l"(__cvta_generic_to_global(src)))
#define CP_COMMIT() asm volatile("cp.async.commit_group;" ::: "memory")
#define CP_WAIT1()  asm volatile("cp.async.wait_group 1;" ::: "memory")
#define CP_WAIT0()  asm volatile("cp.async.wait_group 0;" ::: "memory")

#define LDSM4(r, addr) \
    asm volatile("ldmatrix.sync.aligned.m8n8.x4.shared.b16 {%0,%1,%2,%3}, [%4];" \
                 : "=r"((r)[0]), "=r"((r)[1]), "=r"((r)[2]), "=r"((r)[3]) : "r"(addr))

#define MMA16816(d, a, b) \
    asm volatile("mma.sync.aligned.m16n8k16.row.col.f32.f16.f16.f32 " \
                 "{%0,%1,%2,%3}, {%4,%5,%6,%7}, {%8,%9}, {%0,%1,%2,%3};" \
                 : "+f"((d)[0]), "+f"((d)[1]), "+f"((d)[2]), "+f"((d)[3]) \
                 : "r"((a)[0]), "r"((a)[1]), "r"((a)[2]), "r"((a)[3]), \
                   "r"((b)[0]), "r"((b)[1]))

// ---------------------------------------------------------------------------
// device scratch
// ---------------------------------------------------------------------------
__device__ __align__(256) __half g_W[4096 * KTOT];
__device__ __align__(256) __half g_x[(size_t)T_STEPS * MPAD * INPUTD];
__device__ __align__(256) __half g_h[2][MPAD * HID];
__device__ __align__(16) float g_bias[4 * HID];

// decoder fp16 weights
__device__ __align__(256) __half g_attnWh[WW * HID];
__device__ __align__(256) __half g_combWh[HID * HID];
__device__ __align__(256) __half g_gWih16[3 * HID * HID];
__device__ __align__(256) __half g_gWhh16[3 * HID * HID];
__device__ __align__(256) __half g_ctxT[(size_t)HID * WW];

__device__ __align__(16) float g_u[OUTD];
__device__ __align__(16) float g_hdec[HID];
__device__ __align__(16) float g_comb[HID];
__device__ __align__(16) float g_gi[3 * HID];
__device__ __align__(16) float g_gh[3 * HID];
__device__ __align__(16) float g_v2[HID + OUTD];   // [u; applied]
__device__ float g_sch[WW];

__device__ unsigned g_bcnt = 0;
__device__ volatile unsigned g_bgen = 0;
__device__ unsigned g_bcH[2] = {0, 0};
__device__ volatile unsigned g_bgH[2] = {0, 0};

__device__ __forceinline__ void gbar(unsigned nctas) {
    __syncthreads();
    if (threadIdx.x == 0) {
        __threadfence();
        unsigned gen = g_bgen;
        if (atomicAdd(&g_bcnt, 1u) == nctas - 1u) {
            g_bcnt = 0;
            __threadfence();
            g_bgen = gen + 1u;
        } else {
            while (g_bgen == gen) __nanosleep(32);
        }
        __threadfence();
    }
    __syncthreads();
}

__device__ __forceinline__ void gbarH(int h, unsigned nctas) {
    __syncthreads();
    if (threadIdx.x == 0) {
        __threadfence();
        unsigned gen = g_bgH[h];
        if (atomicAdd(&g_bcH[h], 1u) == nctas - 1u) {
            g_bcH[h] = 0;
            __threadfence();
            g_bgH[h] = gen + 1u;
        } else {
            while (g_bgH[h] == gen) __nanosleep(32);
        }
        __threadfence();
    }
    __syncthreads();
}

__device__ __forceinline__ float sigf(float x)  { return __fdividef(1.f, 1.f + __expf(-x)); }
__device__ __forceinline__ float tanhf_fast(float x) { return 1.f - __fdividef(2.f, __expf(2.f * x) + 1.f); }
__device__ __forceinline__ float warp_red(float s) {
#pragma unroll
    for (int o = 16; o; o >>= 1) s += __shfl_down_sync(0xffffffffu, s, o);
    return s;
}

// fp16-weight x fp32-vector dot, length 1024, lane-strided
__device__ __forceinline__ float dot1024(const __half* __restrict__ w,
                                         const float* __restrict__ v, int lane) {
    float s = 0.f;
    const uint4* w4 = (const uint4*)w;
#pragma unroll
    for (int k = lane; k < 128; k += 32) {
        uint4 u = w4[k];
        const float4* vv = (const float4*)(v + (k << 3));
        float4 va = vv[0], vb = vv[1];
        float2 f0 = __half22float2(*(__half2*)&u.x);
        float2 f1 = __half22float2(*(__half2*)&u.y);
        float2 f2 = __half22float2(*(__half2*)&u.z);
        float2 f3 = __half22float2(*(__half2*)&u.w);
        s += f0.x * va.x + f0.y * va.y + f1.x * va.z + f1.y * va.w
           + f2.x * vb.x + f2.y * vb.y + f3.x * vb.z + f3.y * vb.w;
    }
    return s;
}

// ---------------------------------------------------------------------------
// fragment machinery (32m x 32n warp tile, single-pass fp16)
// ---------------------------------------------------------------------------
struct Frag {
    uint32_t ah[2][4], bh[4][2];
};

__device__ __forceinline__ void load_frags(Frag& f, uint32_t Ah, uint32_t Bh,
                                           int ks, int wr, int wc, int lane) {
#pragma unroll
    for (int mt = 0; mt < 2; mt++) {
        int r = wr * 32 + mt * 16 + (lane & 15);
        uint32_t ch = ((uint32_t)((ks * 2 + (lane >> 4)) ^ (r & 7))) << 4;
        LDSM4(f.ah[mt], Ah + r * 128 + ch);
    }
#pragma unroll
    for (int gp = 0; gp < 2; gp++) {
        int rn = (gp * 2 + (lane >> 4)) * 16 + wc * 8 + (lane & 7);
        uint32_t ch = ((uint32_t)((ks * 2 + ((lane >> 3) & 1)) ^ (rn & 7))) << 4;
        LDSM4(&f.bh[gp * 2][0], Bh + rn * 128 + ch);
    }
}

__device__ __forceinline__ void do_mmas(float (&acc)[2][4][4], const Frag& f) {
#pragma unroll
    for (int mt = 0; mt < 2; mt++)
#pragma unroll
        for (int q = 0; q < 4; q++)
            MMA16816(acc[mt][q], f.ah[mt], f.bh[q]);
}

// ---------------------------------------------------------------------------
// init / convert
// ---------------------------------------------------------------------------
__global__ void k_init(const float* __restrict__ bih, const float* __restrict__ bhh) {
    int i = blockIdx.x * blockDim.x + threadIdx.x;
    int n = MPAD * HID;
    __half z = __float2half(0.f);
    for (int j = i; j < n; j += gridDim.x * blockDim.x) {
        g_h[0][j] = z; g_h[1][j] = z;
    }
    if (i < 4 * HID) g_bias[i] = bih[i] + bhh[i];
}

__global__ void k_conv_w(const float* __restrict__ Whh, const float* __restrict__ Wih) {
    size_t i = (size_t)blockIdx.x * blockDim.x + threadIdx.x;
    if (i >= (size_t)4096 * KTOT) return;
    int r = (int)(i / KTOT);
    int k = (int)(i % KTOT);
    float v = (k < HID) ? Whh[(size_t)r * HID + k] : Wih[(size_t)r * INPUTD + (k - HID)];
    g_W[i] = __float2half(v);
}

__global__ void k_conv_x(const float* __restrict__ data) {
    size_t i = (size_t)blockIdx.x * blockDim.x + threadIdx.x;
    if (i >= (size_t)T_STEPS * MPAD * INPUTD) return;
    int k = (int)(i % INPUTD);
    int b = (int)((i / INPUTD) % MPAD);
    int t = (int)(i / ((size_t)MPAD * INPUTD));
    float v = (b < BATCH) ? data[((size_t)t * BATCH + b) * INPUTD + k] : 0.f;
    g_x[i] = __float2half(v);
}

__global__ void k_conv_dec(const float* __restrict__ attn_W, const float* __restrict__ comb_W,
                           const float* __restrict__ gWih, const float* __restrict__ gWhh) {
    size_t i = (size_t)blockIdx.x * blockDim.x + threadIdx.x;
    const size_t nA = (size_t)WW * HID;
    const size_t nC = (size_t)HID * HID;
    const size_t nG = (size_t)3 * HID * HID;
    if (i < nA) {
        size_t j = i / HID, k = i % HID;
        g_attnWh[i] = __float2half(attn_W[j * (HID + OUTD) + OUTD + k]);
        return;
    }
    i -= nA;
    if (i < nC) {
        size_t r = i / HID, k = i % HID;
        g_combWh[i] = __float2half(comb_W[r * (HID + OUTD) + OUTD + k]);
        return;
    }
    i -= nC;
    if (i < nG) { g_gWih16[i] = __float2half(gWih[i]); return; }
    i -= nG;
    if (i < nG) { g_gWhh16[i] = __float2half(gWhh[i]); return; }
}

// ---------------------------------------------------------------------------
// k_enc: persistent, 240 LSTM steps, ALL weights resident (160KB smem).
// x GEMM folded in as 4 pre-barrier chunks (prefetched); c in registers.
// 128 CTAs x 256 thr; per-m-half barriers (64 CTAs each).
// ---------------------------------------------------------------------------
__global__ __launch_bounds__(256, 1) void k_enc() {
    extern __shared__ __align__(128) char smem[];
    const uint32_t sb  = smem_to_u32(smem);
    const uint32_t sbW = sb;
    const uint32_t sbA = sb + SMW;
    const int tid  = threadIdx.x;
    const int lane = tid & 31;
    const int wid  = tid >> 5;
    const int wr   = wid & 3;
    const int wc   = wid >> 2;
    const int n0   = (blockIdx.x & 63) * 16;
    const int mh   = blockIdx.x >> 6;
    const int m0   = mh * 128;
    const int rowq = lane >> 2;
    const int col2 = (lane & 3) * 2;

    // resident W: 20 chunks x (64 rows x 64 k) = 160 KB  (one commit group)
    for (int i = tid; i < 10240; i += 256) {
        int ci = i >> 9, r = (i >> 3) & 63, ch = i & 7;
        int wrow = (r >> 4) * HID + n0 + (r & 15);
        size_t off = (size_t)wrow * KTOT + ci * 64 + ch * 8;
        uint32_t dst = sbW + ci * 8192 + r * 128 + (((uint32_t)(ch ^ (r & 7))) << 4);
        CP_ASYNC16(dst, g_W + off);
    }
    CP_COMMIT();

    int lb = 0, cbuf = 0;   // FIFO ring counters (load / compute)

    auto loadX = [&](int t, int j) {
        uint32_t base = sbA + lb * 16384; lb = (lb == 2) ? 0 : lb + 1;
#pragma unroll
        for (int i = tid; i < 1024; i += 256) {
            int r = i >> 3, ch = i & 7;
            size_t off = ((size_t)t * MPAD + m0 + r) * INPUTD + j * 64 + ch * 8;
            CP_ASYNC16(base + r * 128 + (((uint32_t)(ch ^ (r & 7))) << 4), g_x + off);
        }
        CP_COMMIT();
    };
    auto loadH = [&](const __half* hIn, int c) {
        uint32_t base = sbA + lb * 16384; lb = (lb == 2) ? 0 : lb + 1;
#pragma unroll
        for (int i = tid; i < 1024; i += 256) {
            int r = i >> 3, ch = i & 7;
            size_t off = (size_t)(m0 + r) * HID + c * 64 + ch * 8;
            CP_ASYNC16(base + r * 128 + (((uint32_t)(ch ^ (r & 7))) << 4), hIn + off);
        }
        CP_COMMIT();
    };

    float acc[2][4][4];
    float creg[2][2][2];
#pragma unroll
    for (int a = 0; a < 2; a++)
#pragma unroll
        for (int b = 0; b < 2; b++)
#pragma unroll
            for (int d = 0; d < 2; d++) creg[a][b][d] = 0.f;
#pragma unroll
    for (int mt = 0; mt < 2; mt++)
#pragma unroll
        for (int q = 0; q < 4; q++)
#pragma unroll
            for (int j = 0; j < 4; j++) acc[mt][q][j] = 0.f;

    auto computeChunk = [&](int wchunk) {
        uint32_t Ah = sbA + cbuf * 16384; cbuf = (cbuf == 2) ? 0 : cbuf + 1;
        uint32_t Bh = sbW + wchunk * 8192;
        Frag fr[2];
        load_frags(fr[0], Ah, Bh, 0, wr, wc, lane);
#pragma unroll
        for (int ks = 0; ks < 4; ks++) {
            if (ks < 3) load_frags(fr[(ks + 1) & 1], Ah, Bh, ks + 1, wr, wc, lane);
            do_mmas(acc, fr[ks & 1]);
        }
    };

    // prologue: x chunks 0,1 of step 0
    loadX(0, 0); loadX(0, 1);

    for (int t = 0; t < T_STEPS; t++) {
        const __half* __restrict__ hIn = g_h[t & 1];

        // ---- pre-barrier x phase (4 chunks, weight chunks 16..19) ----
        CP_WAIT1(); __syncthreads(); loadX(t, 2); computeChunk(16);
        CP_WAIT1(); __syncthreads(); loadX(t, 3); computeChunk(17);
        CP_WAIT1(); __syncthreads(); computeChunk(18);
        CP_WAIT0(); __syncthreads(); computeChunk(19);

        gbarH(mh, 64);   // h(t) now visible

        // ---- post-barrier h phase (16 chunks, weight chunks 0..15) ----
        loadH(hIn, 0); loadH(hIn, 1);
        for (int c = 0; c < 16; c++) {
            CP_WAIT1(); __syncthreads();
            if (c < 14)              loadH(hIn, c + 2);
            else if (t + 1 < T_STEPS) loadX(t + 1, c - 14);   // prefetch next x
            computeChunk(c);
        }

        // ---- fused LSTM gate epilogue (c in registers) ----
        __half* __restrict__ hOut = g_h[(t + 1) & 1];
#pragma unroll
        for (int mt = 0; mt < 2; mt++)
#pragma unroll
            for (int rp = 0; rp < 2; rp++) {
                int m = m0 + wr * 32 + mt * 16 + rowq + rp * 8;
                if (m < BATCH) {
                    int n = n0 + wc * 8 + col2;
                    size_t idx = (size_t)m * HID + n;
                    float2 bi = *(const float2*)&g_bias[n];
                    float2 bf = *(const float2*)&g_bias[HID + n];
                    float2 bg = *(const float2*)&g_bias[2 * HID + n];
                    float2 bo = *(const float2*)&g_bias[3 * HID + n];
                    float h[2];
#pragma unroll
                    for (int j = 0; j < 2; j++) {
                        float gi = acc[mt][0][rp * 2 + j] + (j ? bi.y : bi.x);
                        float gf = acc[mt][1][rp * 2 + j] + (j ? bf.y : bf.x);
                        float gg = acc[mt][2][rp * 2 + j] + (j ? bg.y : bg.x);
                        float go = acc[mt][3][rp * 2 + j] + (j ? bo.y : bo.x);
                        float cn = sigf(gf) * creg[mt][rp][j] + sigf(gi) * tanhf_fast(gg);
                        creg[mt][rp][j] = cn;
                        h[j] = sigf(go) * tanhf_fast(cn);
                    }
                    *(__half2*)&hOut[idx] =
                        __halves2half2(__float2half(h[0]), __float2half(h[1]));
                }
            }

        // reset accumulators for next step
#pragma unroll
        for (int mt = 0; mt < 2; mt++)
#pragma unroll
            for (int q = 0; q < 4; q++)
#pragma unroll
                for (int j = 0; j < 4; j++) acc[mt][q][j] = 0.f;
    }
}

// ---------------------------------------------------------------------------
// k_dec: persistent decoder, 64 CTAs x 256 thr, 5 barriers/step, fp16 weights.
// ---------------------------------------------------------------------------
__global__ __launch_bounds__(256, 1) void k_dec(
    const float* __restrict__ attn_W, const float* __restrict__ attn_b,
    const float* __restrict__ comb_W, const float* __restrict__ comb_b,
    const float* __restrict__ gbih,   const float* __restrict__ gbhh,
    const float* __restrict__ out_W,  const float* __restrict__ out_b,
    float* __restrict__ outp)
{
    __shared__ float s_aw[WW];
    __shared__ float rbuf[8];
    __shared__ float lg[OUTD];

    const int tid  = threadIdx.x;
    const int bid  = blockIdx.x;
    const int lane = tid & 31;
    const int warp = tid >> 5;
    const int gw   = bid * 8 + warp;   // 0..511
    const int gt   = bid * 256 + tid;  // 0..16383

    // init: hdec, u, transposed ctx
    if (gt < HID) g_hdec[gt] = __half2float(g_h[0][(size_t)(BATCH - 1) * HID + gt]);
    if (gt < OUTD) g_u[gt] = 0.125f;
    for (size_t i = gt; i < (size_t)WW * HID; i += NCTA_D * 256) {
        size_t j = i / HID, n = i % HID;
        g_ctxT[n * WW + j] = g_h[0][j * HID + n];
    }
    gbar(NCTA_D);

    auto out_head = [&](int sidx) {
        if (warp < OUTD) {
            const float4* row = (const float4*)(out_W + (size_t)warp * HID);
            const float4* v   = (const float4*)g_hdec;
            float s = 0.f;
            for (int k = lane; k < HID / 4; k += 32) {
                float4 w = row[k], x = v[k];
                s += w.x * x.x + w.y * x.y + w.z * x.z + w.w * x.w;
            }
            s = warp_red(s);
            if (!lane) lg[warp] = s + out_b[warp];
        }
        __syncthreads();
        if (tid == 0) {
            float mx = -1e30f;
#pragma unroll
            for (int i = 0; i < OUTD; i++) mx = fmaxf(mx, lg[i]);
            float sum = 0.f;
#pragma unroll
            for (int i = 0; i < OUTD; i++) sum += __expf(lg[i] - mx);
            float lse = mx + __logf(sum);
#pragma unroll
            for (int i = 0; i < OUTD; i++) {
                float lp = lg[i] - lse;
                outp[sidx * OUTD + i] = lp;
                g_u[i] = lp;
            }
        }
        __syncthreads();
    };

    for (int s = 0; s < NSTEPS; s++) {
        // P1: CTA0 -> prev-step output head (writes u); others -> attn score_h
        if (bid == 0) {
            if (s > 0) out_head(s - 1);
        } else {
            int j = gw - 8;
            if (j < WW) {
                float x = dot1024(g_attnWh + (size_t)j * HID, g_hdec, lane);
                x = warp_red(x);
                if (!lane) g_sch[j] = x;
            }
        }
        gbar(NCTA_D);

        // P2: per-CTA redundant softmax + applied columns
        {
            float x;
            if (tid < WW) {
                float su = 0.f;
#pragma unroll
                for (int k = 0; k < OUTD; k++)
                    su += g_u[k] * attn_W[(size_t)tid * (HID + OUTD) + k];
                x = g_sch[tid] + su + attn_b[tid];
            } else x = -1e30f;
            float mx = x;
#pragma unroll
            for (int o = 16; o; o >>= 1) mx = fmaxf(mx, __shfl_xor_sync(0xffffffffu, mx, o));
            if (!lane) rbuf[warp] = mx;
            __syncthreads();
            float bm = rbuf[0];
#pragma unroll
            for (int i = 1; i < 8; i++) bm = fmaxf(bm, rbuf[i]);
            float e = (tid < WW) ? __expf(x - bm) : 0.f;
            float sm = e;
#pragma unroll
            for (int o = 16; o; o >>= 1) sm += __shfl_xor_sync(0xffffffffu, sm, o);
            __syncthreads();
            if (!lane) rbuf[warp] = sm;
            __syncthreads();
            float tot = 0.f;
#pragma unroll
            for (int i = 0; i < 8; i++) tot += rbuf[i];
            if (tid < WW) s_aw[tid] = e / tot;
            __syncthreads();
#pragma unroll
            for (int rep = 0; rep < 2; rep++) {
                int n = bid * 8 + warp + rep * 512;
                const __half* ct = g_ctxT + (size_t)n * WW;
                float a = 0.f;
                for (int j = lane; j < WW; j += 32) a += s_aw[j] * __half2float(ct[j]);
                a = warp_red(a);
                if (!lane) g_v2[OUTD + n] = a;
            }
            if (bid == 0 && tid < OUTD) g_v2[tid] = g_u[tid];
        }
        gbar(NCTA_D);

        // P3: comb = relu(comb_W @ [u; applied] + b)
#pragma unroll
        for (int rep = 0; rep < 2; rep++) {
            int r = gw + rep * 512;
            float x = dot1024(g_combWh + (size_t)r * HID, g_v2 + OUTD, lane);
            x = warp_red(x);
            if (!lane) {
                float su = 0.f;
#pragma unroll
                for (int k = 0; k < OUTD; k++)
                    su += comb_W[(size_t)r * (HID + OUTD) + k] * g_v2[k];
                g_comb[r] = fmaxf(x + su + comb_b[r], 0.f);
            }
        }
        gbar(NCTA_D);

        // P4: gi / gh (6144 rows over 512 warps)
        for (int rr = gw; rr < 6 * HID; rr += 512) {
            float x;
            if (rr < 3 * HID) x = dot1024(g_gWih16 + (size_t)rr * HID, g_comb, lane);
            else              x = dot1024(g_gWhh16 + (size_t)(rr - 3 * HID) * HID, g_hdec, lane);
            x = warp_red(x);
            if (!lane) {
                if (rr < 3 * HID) g_gi[rr] = x + gbih[rr];
                else              g_gh[rr - 3 * HID] = x + gbhh[rr - 3 * HID];
            }
        }
        gbar(NCTA_D);

        // P5: distributed hdec update
        if (tid < 16) {
            int n = bid * 16 + tid;
            float r  = sigf(g_gi[n] + g_gh[n]);
            float z  = sigf(g_gi[HID + n] + g_gh[HID + n]);
            float nn = tanhf_fast(g_gi[2 * HID + n] + r * g_gh[2 * HID + n]);
            g_hdec[n] = (1.f - z) * nn + z * g_hdec[n];
        }
        gbar(NCTA_D);
    }

    // final output head
    if (bid == 0) out_head(NSTEPS - 1);
}

// ---------------------------------------------------------------------------
// launch
// ---------------------------------------------------------------------------
extern "C" void kernel_launch(void* const* d_in, const int* in_sizes, int n_in,
                              void* d_out, int out_size) {
    const float* data     = (const float*)d_in[0];
    const float* enc_Wih  = (const float*)d_in[1];
    const float* enc_Whh  = (const float*)d_in[2];
    const float* enc_bih  = (const float*)d_in[3];
    const float* enc_bhh  = (const float*)d_in[4];
    const float* attn_W   = (const float*)d_in[5];
    const float* attn_b   = (const float*)d_in[6];
    const float* comb_W   = (const float*)d_in[7];
    const float* comb_b   = (const float*)d_in[8];
    const float* gru_Wih  = (const float*)d_in[9];
    const float* gru_Whh  = (const float*)d_in[10];
    const float* gru_bih  = (const float*)d_in[11];
    const float* gru_bhh  = (const float*)d_in[12];
    const float* out_W    = (const float*)d_in[13];
    const float* out_b    = (const float*)d_in[14];
    float* out = (float*)d_out;

    cudaFuncSetAttribute(k_enc, cudaFuncAttributeMaxDynamicSharedMemorySize, SMEMB);

    k_init<<<1024, 256>>>(enc_bih, enc_bhh);
    k_conv_w<<<(4096 * KTOT + 255) / 256, 256>>>(enc_Whh, enc_Wih);
    k_conv_x<<<(T_STEPS * MPAD * INPUTD + 255) / 256, 256>>>(data);
    {
        size_t ntot = (size_t)WW * HID + (size_t)HID * HID + 2 * (size_t)3 * HID * HID;
        k_conv_dec<<<(int)((ntot + 255) / 256), 256>>>(attn_W, comb_W, gru_Wih, gru_Whh);
    }

    k_enc<<<NCTA, 256, SMEMB>>>();

    k_dec<<<NCTA_D, 256>>>(attn_W, attn_b, comb_W, comb_b,
                           gru_bih, gru_bhh, out_W, out_b, out);
}